// round 7
// baseline (speedup 1.0000x reference)
#include <cuda_runtime.h>
#include <math.h>
#include <cstdint>

#define BATCH  2
#define NSEQ   2048
#define DIM    512
#define HEADS  8
#define DHEAD  32
#define INNER  256
#define ROWS   (BATCH*NSEQ)   // 4096

// ---------------- scratch (device globals: no allocation allowed) ----------
__device__ float g_xn[ROWS*DIM];
__device__ float g_q [BATCH*HEADS*NSEQ*DHEAD];   // pre-scaled by 1/sqrt(32)
__device__ float g_k [BATCH*HEADS*NSEQ*DHEAD];
__device__ float g_v [BATCH*HEADS*NSEQ*DHEAD];
__device__ float g_o [ROWS*INNER];

__device__ __forceinline__ float to_tf32(float x) {
    float r;
    asm("cvt.rna.tf32.f32 %0, %1;" : "=f"(r) : "f"(x));
    return r;
}
__device__ __forceinline__ uint32_t fau(float x) { return __float_as_uint(x); }

// mma.sync m16n8k8 tf32 (sm_80+ portable)
__device__ __forceinline__ void mma_tf32(float* d, const uint32_t* a,
                                         uint32_t b0, uint32_t b1) {
    asm volatile(
        "mma.sync.aligned.m16n8k8.row.col.f32.tf32.tf32.f32 "
        "{%0,%1,%2,%3}, {%4,%5,%6,%7}, {%8,%9}, {%0,%1,%2,%3};"
        : "+f"(d[0]), "+f"(d[1]), "+f"(d[2]), "+f"(d[3])
        : "r"(a[0]), "r"(a[1]), "r"(a[2]), "r"(a[3]), "r"(b0), "r"(b1));
}

// ---------------- 1) LayerNorm ---------------------------------------------
__global__ __launch_bounds__(128) void ln_kernel(const float* __restrict__ x,
                                                 const float* __restrict__ gamma)
{
    int row = blockIdx.x;
    int t   = threadIdx.x;
    const float* xr = x + (size_t)row*DIM;

    float4 xv = *(const float4*)(xr + t*4);
    float s  = xv.x + xv.y + xv.z + xv.w;
    float ss = xv.x*xv.x + xv.y*xv.y + xv.z*xv.z + xv.w*xv.w;

    #pragma unroll
    for (int ofs = 16; ofs >= 1; ofs >>= 1) {
        s  += __shfl_xor_sync(0xffffffffu, s,  ofs);
        ss += __shfl_xor_sync(0xffffffffu, ss, ofs);
    }
    __shared__ float rs[4], rss[4];
    int lane = t & 31, wid = t >> 5;
    if (lane == 0) { rs[wid] = s; rss[wid] = ss; }
    __syncthreads();
    s  = rs[0]  + rs[1]  + rs[2]  + rs[3];
    ss = rss[0] + rss[1] + rss[2] + rss[3];

    float mu   = s * (1.0f/DIM);
    float var  = ss * (1.0f/DIM) - mu*mu;
    float rstd = rsqrtf(var + 1e-5f);

    float4 g = *(const float4*)(gamma + t*4);
    float4 o;
    o.x = (xv.x - mu) * rstd * g.x;
    o.y = (xv.y - mu) * rstd * g.y;
    o.z = (xv.z - mu) * rstd * g.z;
    o.w = (xv.w - mu) * rstd * g.w;
    *(float4*)(g_xn + (size_t)row*DIM + t*4) = o;
}

// ============ split-tf32 tensor GEMM core (128x64 tile, BK=32) ==============
// sA frag-major: (ms*4+ks)*128 + lane*4 + reg   (16KB)
// sB frag-major: (ns*4+ks)*64  + lane*2 + reg   ( 8KB)
// a-frag element A[fr][fd] (fr<16, fd<8): lane=((fr&7)<<2)|(fd&3),
//   reg=((fr>>3)&1) | (((fd>>2)&1)<<1)
// b-frag element B[fk][fn]: lane=(fn<<2)|(fk&3), reg=(fk>>2)&1
// (layouts validated by the passing R5 attention kernel)

#define GEMM_TC_BODY(APTR, BPTR, KDIM, NSTRIDE)                                   \
    __shared__ float sA[4096];                                                    \
    __shared__ float sB[2048];                                                    \
    int tid  = threadIdx.x;                                                       \
    int lane = tid & 31;                                                          \
    int w    = tid >> 5;                                                          \
    int wm   = w >> 1, wn = w & 1;                                                \
    int g    = lane >> 2, q = lane & 3;                                           \
    int bm   = blockIdx.y * 128;                                                  \
    int bn   = blockIdx.x * 64;                                                   \
    float c[2][4][4] = {};                                                        \
    for (int kt = 0; kt < (KDIM); kt += 32) {                                     \
        _Pragma("unroll")                                                         \
        for (int u = 0; u < 4; ++u) {                                             \
            int idx = u*256 + tid;                                                \
            int row = idx >> 3, dg = (idx & 7) * 4;                               \
            float4 av = *(const float4*)((APTR) + (size_t)(bm+row)*(KDIM) + kt + dg); \
            _Pragma("unroll")                                                     \
            for (int e = 0; e < 4; ++e) {                                         \
                int d = dg + e;                                                   \
                float val = (e==0)?av.x:(e==1)?av.y:(e==2)?av.z:av.w;             \
                int ms = row >> 4, ks = d >> 3;                                   \
                int fr = row & 15, fd = d & 7;                                    \
                int ln = ((fr & 7) << 2) | (fd & 3);                              \
                int rg = ((fr >> 3) & 1) | (((fd >> 2) & 1) << 1);                \
                sA[(ms*4+ks)*128 + ln*4 + rg] = val;                              \
            }                                                                     \
        }                                                                         \
        _Pragma("unroll")                                                         \
        for (int u = 0; u < 2; ++u) {                                             \
            int idx = u*256 + tid;                                                \
            int k = idx >> 4, ng = (idx & 15) * 4;                                \
            float4 bv = *(const float4*)((BPTR) + (size_t)(kt+k)*(NSTRIDE) + bn + ng); \
            _Pragma("unroll")                                                     \
            for (int e = 0; e < 4; ++e) {                                         \
                int n = ng + e;                                                   \
                float val = (e==0)?bv.x:(e==1)?bv.y:(e==2)?bv.z:bv.w;             \
                int ns = n >> 3, ks = k >> 3;                                     \
                int fk = k & 7, fn = n & 7;                                       \
                int ln = (fn << 2) | (fk & 3);                                    \
                int rg = (fk >> 2) & 1;                                           \
                sB[(ns*4+ks)*64 + ln*2 + rg] = val;                               \
            }                                                                     \
        }                                                                         \
        __syncthreads();                                                          \
        _Pragma("unroll")                                                         \
        for (int ks = 0; ks < 4; ++ks) {                                          \
            uint32_t ah[2][4], al[2][4];                                          \
            _Pragma("unroll")                                                     \
            for (int i = 0; i < 2; ++i) {                                         \
                float4 av = *(const float4*)(&sA[((wm*2+i)*4+ks)*128 + lane*4]);  \
                float h0 = to_tf32(av.x), h1 = to_tf32(av.y);                     \
                float h2 = to_tf32(av.z), h3 = to_tf32(av.w);                     \
                ah[i][0]=fau(h0); ah[i][1]=fau(h1); ah[i][2]=fau(h2); ah[i][3]=fau(h3); \
                al[i][0]=fau(to_tf32(av.x-h0)); al[i][1]=fau(to_tf32(av.y-h1));   \
                al[i][2]=fau(to_tf32(av.z-h2)); al[i][3]=fau(to_tf32(av.w-h3));   \
            }                                                                     \
            uint32_t bh[4][2], bl[4][2];                                          \
            _Pragma("unroll")                                                     \
            for (int j = 0; j < 4; ++j) {                                         \
                float2 bv = *(const float2*)(&sB[((wn*4+j)*4+ks)*64 + lane*2]);   \
                float h0 = to_tf32(bv.x), h1 = to_tf32(bv.y);                     \
                bh[j][0]=fau(h0); bh[j][1]=fau(h1);                               \
                bl[j][0]=fau(to_tf32(bv.x-h0)); bl[j][1]=fau(to_tf32(bv.y-h1));   \
            }                                                                     \
            _Pragma("unroll")                                                     \
            for (int i = 0; i < 2; ++i)                                           \
                _Pragma("unroll")                                                 \
                for (int j = 0; j < 4; ++j) {                                     \
                    mma_tf32(c[i][j], ah[i], bh[j][0], bh[j][1]);                 \
                    mma_tf32(c[i][j], ah[i], bl[j][0], bl[j][1]);                 \
                    mma_tf32(c[i][j], al[i], bh[j][0], bh[j][1]);                 \
                }                                                                 \
        }                                                                         \
        __syncthreads();                                                          \
    }

// ---------------- 2) QKV GEMM via split tf32 mma ----------------------------
__global__ __launch_bounds__(256) void gemm_qkv_tc(const float* __restrict__ B)
{
    GEMM_TC_BODY(g_xn, B, DIM, 3*INNER)

    // epilogue: scatter into g_q/g_k/g_v head-major, q pre-scaled
    #pragma unroll
    for (int i = 0; i < 2; ++i) {
        int row0 = bm + (wm*2+i)*16 + g;
        #pragma unroll
        for (int j = 0; j < 4; ++j) {
            int col  = bn + (wn*4+j)*8 + 2*q;
            int part = col >> 8;
            int rest = col & 255;
            int h    = rest >> 5;
            int d    = rest & 31;
            float* dst = (part == 0) ? g_q : (part == 1) ? g_k : g_v;
            float scl  = (part == 0) ? 0.17677669529663687f : 1.0f;
            #pragma unroll
            for (int r = 0; r < 2; ++r) {
                int rm = row0 + r*8;
                int b_ = rm >> 11;
                int n  = rm & 2047;
                float2 o;
                o.x = c[i][j][r*2+0] * scl;
                o.y = c[i][j][r*2+1] * scl;
                *(float2*)(dst + ((size_t)((b_*HEADS + h)*NSEQ + n))*DHEAD + d) = o;
            }
        }
    }
}

// ---------------- 4) Out projection via split tf32 mma ----------------------
__global__ __launch_bounds__(256) void gemm_out_tc(const float* __restrict__ B,
                                                   const float* __restrict__ bvec,
                                                   float* __restrict__ out)
{
    GEMM_TC_BODY(g_o, B, INNER, DIM)

    #pragma unroll
    for (int i = 0; i < 2; ++i) {
        int row0 = bm + (wm*2+i)*16 + g;
        #pragma unroll
        for (int j = 0; j < 4; ++j) {
            int col = bn + (wn*4+j)*8 + 2*q;
            float2 bb = *(const float2*)(bvec + col);
            #pragma unroll
            for (int r = 0; r < 2; ++r) {
                int rm = row0 + r*8;
                float2 o;
                o.x = c[i][j][r*2+0] + bb.x;
                o.y = c[i][j][r*2+1] + bb.y;
                *(float2*)(out + (size_t)rm*DIM + col) = o;
            }
        }
    }
}

// ---------------- 3) Attention via mma.sync tf32 (proven R5) ----------------
__global__ __launch_bounds__(256) void attn_mma_kernel(const float* __restrict__ bias)
{
    __shared__ float sbuf[4224];

    int tid  = threadIdx.x;
    int w    = tid >> 5;
    int lane = tid & 31;
    int g    = lane >> 2;
    int q    = lane & 3;
    int bh   = blockIdx.y;
    int i0   = blockIdx.x * 128;
    int h    = bh & 7;
    int b_   = bh >> 3;

    const float* qb = g_q + (size_t)bh*NSEQ*DHEAD;
    const float* kb = g_k + (size_t)bh*NSEQ*DHEAD;
    const float* vb = g_v + (size_t)bh*NSEQ*DHEAD;

    #pragma unroll
    for (int u = 0; u < 4; ++u) {
        int f   = u*256 + tid;
        int row = f >> 3;
        int dg  = (f & 7) * 4;
        float4 qv = *(const float4*)(qb + (size_t)(i0+row)*DHEAD + dg);
        float* s  = &sbuf[row*33 + dg];
        s[0] = qv.x; s[1] = qv.y; s[2] = qv.z; s[3] = qv.w;
    }
    __syncthreads();

    uint32_t qa[4][4];
    {
        int r0 = w*16 + g;
        #pragma unroll
        for (int ks = 0; ks < 4; ++ks) {
            qa[ks][0] = fau(to_tf32(sbuf[(r0  )*33 + ks*8 + q    ]));
            qa[ks][1] = fau(to_tf32(sbuf[(r0+8)*33 + ks*8 + q    ]));
            qa[ks][2] = fau(to_tf32(sbuf[(r0  )*33 + ks*8 + q + 4]));
            qa[ks][3] = fau(to_tf32(sbuf[(r0+8)*33 + ks*8 + q + 4]));
        }
    }
    __syncthreads();

    const float* bp0 = bias + (size_t)h*NSEQ*NSEQ + (size_t)(i0 + w*16 + g)*NSEQ;
    const float* bp1 = bp0 + 8*NSEQ;

    float oc[4][4] = {};
    float lsum0 = 0.f, lsum1 = 0.f;

    for (int jt = 0; jt < NSEQ; jt += 64) {
        #pragma unroll
        for (int u = 0; u < 2; ++u) {
            int f   = u*256 + tid;
            int row = f >> 3;
            int dg  = (f & 7) * 4;
            float4 kv = *(const float4*)(kb + (size_t)(jt+row)*DHEAD + dg);
            float4 vv = *(const float4*)(vb + (size_t)(jt+row)*DHEAD + dg);
            #pragma unroll
            for (int e = 0; e < 4; ++e) {
                int d  = dg + e;
                float kval = to_tf32((e==0)?kv.x:(e==1)?kv.y:(e==2)?kv.z:kv.w);
                float vval = to_tf32((e==0)?vv.x:(e==1)?vv.y:(e==2)?vv.z:vv.w);
                sbuf[(((d>>3)*8 + (row>>3))*32 + (((row&7)<<2)|(d&3)))*2 + ((d>>2)&1)] = kval;
                sbuf[2048 + (((row>>3)*4 + (d>>3))*32 + (((d&7)<<2)|(row&3)))*2 + ((row>>2)&1)] = vval;
            }
        }
        __syncthreads();

        float c[8][4] = {};
        #pragma unroll
        for (int js = 0; js < 8; ++js) {
            #pragma unroll
            for (int ks = 0; ks < 4; ++ks) {
                float2 kf = *(const float2*)(&sbuf[(ks*8+js)*64 + lane*2]);
                mma_tf32(c[js], qa[ks], fau(kf.x), fau(kf.y));
            }
        }

        #pragma unroll
        for (int s = 0; s < 8; ++s) {
            float2 bv0 = *(const float2*)(bp0 + jt + s*8 + 2*q);
            float2 bv1 = *(const float2*)(bp1 + jt + s*8 + 2*q);
            float p0 = __expf(c[s][0] + bv0.x);
            float p1 = __expf(c[s][1] + bv0.y);
            float p2 = __expf(c[s][2] + bv1.x);
            float p3 = __expf(c[s][3] + bv1.y);
            lsum0 += p0 + p1;
            lsum1 += p2 + p3;
            c[s][0] = to_tf32(p0); c[s][1] = to_tf32(p1);
            c[s][2] = to_tf32(p2); c[s][3] = to_tf32(p3);
        }

        #pragma unroll
        for (int ks = 0; ks < 8; ++ks) {
            int src0 = (lane & ~3) | (q >> 1);
            int src1 = src0 + 2;
            float t0 = __shfl_sync(0xffffffffu, c[ks][0], src0);
            float t1 = __shfl_sync(0xffffffffu, c[ks][1], src0);
            float t2 = __shfl_sync(0xffffffffu, c[ks][2], src0);
            float t3 = __shfl_sync(0xffffffffu, c[ks][3], src0);
            float u0 = __shfl_sync(0xffffffffu, c[ks][0], src1);
            float u1 = __shfl_sync(0xffffffffu, c[ks][1], src1);
            float u2 = __shfl_sync(0xffffffffu, c[ks][2], src1);
            float u3 = __shfl_sync(0xffffffffu, c[ks][3], src1);
            bool odd = (q & 1);
            uint32_t pa[4];
            pa[0] = fau(odd ? t1 : t0);
            pa[1] = fau(odd ? t3 : t2);
            pa[2] = fau(odd ? u1 : u0);
            pa[3] = fau(odd ? u3 : u2);
            #pragma unroll
            for (int ns = 0; ns < 4; ++ns) {
                float2 vf = *(const float2*)(&sbuf[2048 + (ks*4+ns)*64 + lane*2]);
                mma_tf32(oc[ns], pa, fau(vf.x), fau(vf.y));
            }
        }
        __syncthreads();
    }

    #pragma unroll
    for (int ofs = 1; ofs <= 2; ofs <<= 1) {
        lsum0 += __shfl_xor_sync(0xffffffffu, lsum0, ofs);
        lsum1 += __shfl_xor_sync(0xffffffffu, lsum1, ofs);
    }
    float inv0 = 1.0f / lsum0;
    float inv1 = 1.0f / lsum1;

    int r0 = i0 + w*16 + g;
    float* o0 = g_o + ((size_t)(b_*NSEQ + r0    ))*INNER + h*DHEAD;
    float* o1 = g_o + ((size_t)(b_*NSEQ + r0 + 8))*INNER + h*DHEAD;
    #pragma unroll
    for (int ns = 0; ns < 4; ++ns) {
        float2 a, b;
        a.x = oc[ns][0]*inv0; a.y = oc[ns][1]*inv0;
        b.x = oc[ns][2]*inv1; b.y = oc[ns][3]*inv1;
        *(float2*)(o0 + ns*8 + 2*q) = a;
        *(float2*)(o1 + ns*8 + 2*q) = b;
    }
}

// ---------------- launch ----------------------------------------------------
extern "C" void kernel_launch(void* const* d_in, const int* in_sizes, int n_in,
                              void* d_out, int out_size)
{
    const float* x        = (const float*)d_in[0];
    const float* rel_bias = (const float*)d_in[1];
    const float* ln_scale = (const float*)d_in[2];
    const float* w_qkv    = (const float*)d_in[3];
    const float* w_out    = (const float*)d_in[4];
    const float* b_out    = (const float*)d_in[5];
    float*       out      = (float*)d_out;

    ln_kernel<<<ROWS, 128>>>(x, ln_scale);

    dim3 g1(3*INNER/64, ROWS/128);    // (12, 32)
    gemm_qkv_tc<<<g1, 256>>>(w_qkv);

    dim3 g2(NSEQ/128, BATCH*HEADS);   // (16, 16)
    attn_mma_kernel<<<g2, 256>>>(rel_bias);

    dim3 g3(DIM/64, ROWS/128);        // (8, 32)
    gemm_out_tc<<<g3, 256>>>(w_out, b_out, out);
}

// round 8
// speedup vs baseline: 1.2584x; 1.2584x over previous
#include <cuda_runtime.h>
#include <math.h>
#include <cstdint>

#define BATCH  2
#define NSEQ   2048
#define DIM    512
#define HEADS  8
#define DHEAD  32
#define INNER  256
#define ROWS   (BATCH*NSEQ)   // 4096

// ---------------- scratch (device globals: no allocation allowed) ----------
__device__ float g_xn[ROWS*DIM];
__device__ float g_q [BATCH*HEADS*NSEQ*DHEAD];   // pre-scaled by 1/sqrt(32)
__device__ float g_k [BATCH*HEADS*NSEQ*DHEAD];
__device__ float g_v [BATCH*HEADS*NSEQ*DHEAD];
__device__ float g_o [ROWS*INNER];

__device__ __forceinline__ float to_tf32(float x) {
    float r;
    asm("cvt.rna.tf32.f32 %0, %1;" : "=f"(r) : "f"(x));
    return r;
}
__device__ __forceinline__ uint32_t fau(float x) { return __float_as_uint(x); }

__device__ __forceinline__ uint32_t smem_u32(const void* p) {
    uint32_t a;
    asm("{ .reg .u64 t; cvta.to.shared.u64 t, %1; cvt.u32.u64 %0, t; }" : "=r"(a) : "l"(p));
    return a;
}
__device__ __forceinline__ void cp16(uint32_t saddr, const void* g) {
    asm volatile("cp.async.cg.shared.global [%0], [%1], 16;" :: "r"(saddr), "l"(g));
}
#define CP_COMMIT() asm volatile("cp.async.commit_group;" ::: "memory")
#define CP_WAIT(n)  asm volatile("cp.async.wait_group %0;" :: "n"(n) : "memory")

// mma.sync m16n8k8 tf32 (sm_80+ portable)
__device__ __forceinline__ void mma_tf32(float* d, const uint32_t* a,
                                         uint32_t b0, uint32_t b1) {
    asm volatile(
        "mma.sync.aligned.m16n8k8.row.col.f32.tf32.tf32.f32 "
        "{%0,%1,%2,%3}, {%4,%5,%6,%7}, {%8,%9}, {%0,%1,%2,%3};"
        : "+f"(d[0]), "+f"(d[1]), "+f"(d[2]), "+f"(d[3])
        : "r"(a[0]), "r"(a[1]), "r"(a[2]), "r"(a[3]), "r"(b0), "r"(b1));
}

// ---------------- 1) LayerNorm ---------------------------------------------
__global__ __launch_bounds__(128) void ln_kernel(const float* __restrict__ x,
                                                 const float* __restrict__ gamma)
{
    int row = blockIdx.x;
    int t   = threadIdx.x;
    const float* xr = x + (size_t)row*DIM;

    float4 xv = *(const float4*)(xr + t*4);
    float s  = xv.x + xv.y + xv.z + xv.w;
    float ss = xv.x*xv.x + xv.y*xv.y + xv.z*xv.z + xv.w*xv.w;

    #pragma unroll
    for (int ofs = 16; ofs >= 1; ofs >>= 1) {
        s  += __shfl_xor_sync(0xffffffffu, s,  ofs);
        ss += __shfl_xor_sync(0xffffffffu, ss, ofs);
    }
    __shared__ float rs[4], rss[4];
    int lane = t & 31, wid = t >> 5;
    if (lane == 0) { rs[wid] = s; rss[wid] = ss; }
    __syncthreads();
    s  = rs[0]  + rs[1]  + rs[2]  + rs[3];
    ss = rss[0] + rss[1] + rss[2] + rss[3];

    float mu   = s * (1.0f/DIM);
    float var  = ss * (1.0f/DIM) - mu*mu;
    float rstd = rsqrtf(var + 1e-5f);

    float4 g = *(const float4*)(gamma + t*4);
    float4 o;
    o.x = (xv.x - mu) * rstd * g.x;
    o.y = (xv.y - mu) * rstd * g.y;
    o.z = (xv.z - mu) * rstd * g.z;
    o.w = (xv.w - mu) * rstd * g.w;
    *(float4*)(g_xn + (size_t)row*DIM + t*4) = o;
}

// ======= split-tf32 tensor GEMM core: cp.async double-buffered ==============
// Block tile 128x64, BK=32, 256 threads = 8 warps (wm=w>>1 in 0..3, wn=w&1).
// smem per stage: A row-major [128][32] XOR-swizzled (col4 ^= row&7),
//                 B row-major [32][64]  XOR-swizzled (col4 ^= (k&3)<<1).
// a-frag reg r: A[ms*16 + g + 8*(r&1)][ks*8 + q + 4*(r>>1)]
// b-frag reg r: B[ks*8 + q + 4*r][ns*8 + g]
// (fragment<->matrix relations validated numerically by the R5 attn kernel)

template<int KDIM, int NSTRIDE>
__device__ __forceinline__ void gemm_tc_core(const float* __restrict__ A,
                                             const float* __restrict__ Bm,
                                             float (*sm)[6144],
                                             float c[2][4][4])
{
    const int tid  = threadIdx.x;
    const int lane = tid & 31;
    const int w    = tid >> 5;
    const int wm   = w >> 1, wn = w & 1;
    const int g    = lane >> 2, q = lane & 3;
    const int bm   = blockIdx.y * 128;
    const int bn   = blockIdx.x * 64;
    const int KT   = KDIM / 32;

    const int ar  = tid >> 3;        // A sub-row (0..31), +32u
    const int ac4 = tid & 7;         // A float4 col
    const int br  = tid >> 4;        // B sub-row (0..15), +16u
    const int bc4 = tid & 15;        // B float4 col

    uint32_t sbase[2] = { smem_u32(&sm[0][0]), smem_u32(&sm[1][0]) };

    // ---- prefetch tile 0 into stage 0 ----
    {
        #pragma unroll
        for (int u = 0; u < 4; ++u) {
            int row = u*32 + ar;
            int sc4 = ac4 ^ (row & 7);
            cp16(sbase[0] + (uint32_t)(row*8 + sc4)*16,
                 A + (size_t)(bm+row)*KDIM + ac4*4);
        }
        #pragma unroll
        for (int u = 0; u < 2; ++u) {
            int k   = u*16 + br;
            int sc4 = bc4 ^ ((k & 3) << 1);
            cp16(sbase[0] + 16384u + (uint32_t)(k*16 + sc4)*16,
                 Bm + (size_t)k*NSTRIDE + bn + bc4*4);
        }
        CP_COMMIT();
    }

    for (int t = 0; t < KT; ++t) {
        if (t + 1 < KT) {
            int kt = (t+1) * 32;
            uint32_t sb = sbase[(t+1) & 1];
            #pragma unroll
            for (int u = 0; u < 4; ++u) {
                int row = u*32 + ar;
                int sc4 = ac4 ^ (row & 7);
                cp16(sb + (uint32_t)(row*8 + sc4)*16,
                     A + (size_t)(bm+row)*KDIM + kt + ac4*4);
            }
            #pragma unroll
            for (int u = 0; u < 2; ++u) {
                int k   = u*16 + br;
                int sc4 = bc4 ^ ((k & 3) << 1);
                cp16(sb + 16384u + (uint32_t)(k*16 + sc4)*16,
                     Bm + (size_t)(kt+k)*NSTRIDE + bn + bc4*4);
            }
            CP_COMMIT();
            CP_WAIT(1);
        } else {
            CP_WAIT(0);
        }
        __syncthreads();

        const float* sA = &sm[t & 1][0];
        const float* sB = &sm[t & 1][4096];

        #pragma unroll
        for (int ks = 0; ks < 4; ++ks) {
            uint32_t ah[2][4], al[2][4];
            #pragma unroll
            for (int i = 0; i < 2; ++i) {
                #pragma unroll
                for (int r = 0; r < 4; ++r) {
                    int row = wm*32 + i*16 + g + 8*(r & 1);
                    int c4  = (ks*2 + (r >> 1)) ^ (row & 7);
                    float v = sA[row*32 + c4*4 + q];
                    float h = to_tf32(v);
                    ah[i][r] = fau(h);
                    al[i][r] = fau(to_tf32(v - h));
                }
            }
            uint32_t bh[4][2], bl[4][2];
            #pragma unroll
            for (int j = 0; j < 4; ++j) {
                #pragma unroll
                for (int r = 0; r < 2; ++r) {
                    int k  = ks*8 + q + 4*r;
                    int n  = wn*32 + j*8 + g;
                    int c4 = (n >> 2) ^ ((k & 3) << 1);
                    float v = sB[k*64 + c4*4 + (n & 3)];
                    float h = to_tf32(v);
                    bh[j][r] = fau(h);
                    bl[j][r] = fau(to_tf32(v - h));
                }
            }
            #pragma unroll
            for (int i = 0; i < 2; ++i)
                #pragma unroll
                for (int j = 0; j < 4; ++j) {
                    mma_tf32(c[i][j], ah[i], bh[j][0], bh[j][1]);
                    mma_tf32(c[i][j], ah[i], bl[j][0], bl[j][1]);
                    mma_tf32(c[i][j], al[i], bh[j][0], bh[j][1]);
                }
        }
        __syncthreads();
    }
}

// ---------------- 2) QKV GEMM via pipelined split tf32 mma -------------------
__global__ __launch_bounds__(256) void gemm_qkv_tc(const float* __restrict__ B)
{
    __shared__ float sm[2][6144];
    float c[2][4][4] = {};
    gemm_tc_core<DIM, 3*INNER>(g_xn, B, sm, c);

    int tid  = threadIdx.x;
    int lane = tid & 31;
    int w    = tid >> 5;
    int wm   = w >> 1, wn = w & 1;
    int g    = lane >> 2, q = lane & 3;
    int bm   = blockIdx.y * 128;
    int bn   = blockIdx.x * 64;

    #pragma unroll
    for (int i = 0; i < 2; ++i) {
        int row0 = bm + wm*32 + i*16 + g;
        #pragma unroll
        for (int j = 0; j < 4; ++j) {
            int col  = bn + wn*32 + j*8 + 2*q;
            int part = col >> 8;
            int rest = col & 255;
            int h    = rest >> 5;
            int d    = rest & 31;
            float* dst = (part == 0) ? g_q : (part == 1) ? g_k : g_v;
            float scl  = (part == 0) ? 0.17677669529663687f : 1.0f;
            #pragma unroll
            for (int r = 0; r < 2; ++r) {
                int rm = row0 + r*8;
                int b_ = rm >> 11;
                int n  = rm & 2047;
                float2 o;
                o.x = c[i][j][r*2+0] * scl;
                o.y = c[i][j][r*2+1] * scl;
                *(float2*)(dst + ((size_t)((b_*HEADS + h)*NSEQ + n))*DHEAD + d) = o;
            }
        }
    }
}

// ---------------- 4) Out projection via pipelined split tf32 mma -------------
__global__ __launch_bounds__(256) void gemm_out_tc(const float* __restrict__ B,
                                                   const float* __restrict__ bvec,
                                                   float* __restrict__ out)
{
    __shared__ float sm[2][6144];
    float c[2][4][4] = {};
    gemm_tc_core<INNER, DIM>(g_o, B, sm, c);

    int tid  = threadIdx.x;
    int lane = tid & 31;
    int w    = tid >> 5;
    int wm   = w >> 1, wn = w & 1;
    int g    = lane >> 2, q = lane & 3;
    int bm   = blockIdx.y * 128;
    int bn   = blockIdx.x * 64;

    #pragma unroll
    for (int i = 0; i < 2; ++i) {
        int row0 = bm + wm*32 + i*16 + g;
        #pragma unroll
        for (int j = 0; j < 4; ++j) {
            int col = bn + wn*32 + j*8 + 2*q;
            float2 bb = *(const float2*)(bvec + col);
            #pragma unroll
            for (int r = 0; r < 2; ++r) {
                int rm = row0 + r*8;
                float2 o;
                o.x = c[i][j][r*2+0] + bb.x;
                o.y = c[i][j][r*2+1] + bb.y;
                *(float2*)(out + (size_t)rm*DIM + col) = o;
            }
        }
    }
}

// ---------------- 3) Attention via mma.sync tf32 (proven R5) ----------------
__global__ __launch_bounds__(256) void attn_mma_kernel(const float* __restrict__ bias)
{
    __shared__ float sbuf[4224];

    int tid  = threadIdx.x;
    int w    = tid >> 5;
    int lane = tid & 31;
    int g    = lane >> 2;
    int q    = lane & 3;
    int bh   = blockIdx.y;
    int i0   = blockIdx.x * 128;
    int h    = bh & 7;
    int b_   = bh >> 3;

    const float* qb = g_q + (size_t)bh*NSEQ*DHEAD;
    const float* kb = g_k + (size_t)bh*NSEQ*DHEAD;
    const float* vb = g_v + (size_t)bh*NSEQ*DHEAD;

    #pragma unroll
    for (int u = 0; u < 4; ++u) {
        int f   = u*256 + tid;
        int row = f >> 3;
        int dg  = (f & 7) * 4;
        float4 qv = *(const float4*)(qb + (size_t)(i0+row)*DHEAD + dg);
        float* s  = &sbuf[row*33 + dg];
        s[0] = qv.x; s[1] = qv.y; s[2] = qv.z; s[3] = qv.w;
    }
    __syncthreads();

    uint32_t qa[4][4];
    {
        int r0 = w*16 + g;
        #pragma unroll
        for (int ks = 0; ks < 4; ++ks) {
            qa[ks][0] = fau(to_tf32(sbuf[(r0  )*33 + ks*8 + q    ]));
            qa[ks][1] = fau(to_tf32(sbuf[(r0+8)*33 + ks*8 + q    ]));
            qa[ks][2] = fau(to_tf32(sbuf[(r0  )*33 + ks*8 + q + 4]));
            qa[ks][3] = fau(to_tf32(sbuf[(r0+8)*33 + ks*8 + q + 4]));
        }
    }
    __syncthreads();

    const float* bp0 = bias + (size_t)h*NSEQ*NSEQ + (size_t)(i0 + w*16 + g)*NSEQ;
    const float* bp1 = bp0 + 8*NSEQ;

    float oc[4][4] = {};
    float lsum0 = 0.f, lsum1 = 0.f;

    for (int jt = 0; jt < NSEQ; jt += 64) {
        #pragma unroll
        for (int u = 0; u < 2; ++u) {
            int f   = u*256 + tid;
            int row = f >> 3;
            int dg  = (f & 7) * 4;
            float4 kv = *(const float4*)(kb + (size_t)(jt+row)*DHEAD + dg);
            float4 vv = *(const float4*)(vb + (size_t)(jt+row)*DHEAD + dg);
            #pragma unroll
            for (int e = 0; e < 4; ++e) {
                int d  = dg + e;
                float kval = to_tf32((e==0)?kv.x:(e==1)?kv.y:(e==2)?kv.z:kv.w);
                float vval = to_tf32((e==0)?vv.x:(e==1)?vv.y:(e==2)?vv.z:vv.w);
                sbuf[(((d>>3)*8 + (row>>3))*32 + (((row&7)<<2)|(d&3)))*2 + ((d>>2)&1)] = kval;
                sbuf[2048 + (((row>>3)*4 + (d>>3))*32 + (((d&7)<<2)|(row&3)))*2 + ((row>>2)&1)] = vval;
            }
        }
        __syncthreads();

        float c[8][4] = {};
        #pragma unroll
        for (int js = 0; js < 8; ++js) {
            #pragma unroll
            for (int ks = 0; ks < 4; ++ks) {
                float2 kf = *(const float2*)(&sbuf[(ks*8+js)*64 + lane*2]);
                mma_tf32(c[js], qa[ks], fau(kf.x), fau(kf.y));
            }
        }

        #pragma unroll
        for (int s = 0; s < 8; ++s) {
            float2 bv0 = *(const float2*)(bp0 + jt + s*8 + 2*q);
            float2 bv1 = *(const float2*)(bp1 + jt + s*8 + 2*q);
            float p0 = __expf(c[s][0] + bv0.x);
            float p1 = __expf(c[s][1] + bv0.y);
            float p2 = __expf(c[s][2] + bv1.x);
            float p3 = __expf(c[s][3] + bv1.y);
            lsum0 += p0 + p1;
            lsum1 += p2 + p3;
            c[s][0] = to_tf32(p0); c[s][1] = to_tf32(p1);
            c[s][2] = to_tf32(p2); c[s][3] = to_tf32(p3);
        }

        #pragma unroll
        for (int ks = 0; ks < 8; ++ks) {
            int src0 = (lane & ~3) | (q >> 1);
            int src1 = src0 + 2;
            float t0 = __shfl_sync(0xffffffffu, c[ks][0], src0);
            float t1 = __shfl_sync(0xffffffffu, c[ks][1], src0);
            float t2 = __shfl_sync(0xffffffffu, c[ks][2], src0);
            float t3 = __shfl_sync(0xffffffffu, c[ks][3], src0);
            float u0 = __shfl_sync(0xffffffffu, c[ks][0], src1);
            float u1 = __shfl_sync(0xffffffffu, c[ks][1], src1);
            float u2 = __shfl_sync(0xffffffffu, c[ks][2], src1);
            float u3 = __shfl_sync(0xffffffffu, c[ks][3], src1);
            bool odd = (q & 1);
            uint32_t pa[4];
            pa[0] = fau(odd ? t1 : t0);
            pa[1] = fau(odd ? t3 : t2);
            pa[2] = fau(odd ? u1 : u0);
            pa[3] = fau(odd ? u3 : u2);
            #pragma unroll
            for (int ns = 0; ns < 4; ++ns) {
                float2 vf = *(const float2*)(&sbuf[2048 + (ks*4+ns)*64 + lane*2]);
                mma_tf32(oc[ns], pa, fau(vf.x), fau(vf.y));
            }
        }
        __syncthreads();
    }

    #pragma unroll
    for (int ofs = 1; ofs <= 2; ofs <<= 1) {
        lsum0 += __shfl_xor_sync(0xffffffffu, lsum0, ofs);
        lsum1 += __shfl_xor_sync(0xffffffffu, lsum1, ofs);
    }
    float inv0 = 1.0f / lsum0;
    float inv1 = 1.0f / lsum1;

    int r0 = i0 + w*16 + g;
    float* o0 = g_o + ((size_t)(b_*NSEQ + r0    ))*INNER + h*DHEAD;
    float* o1 = g_o + ((size_t)(b_*NSEQ + r0 + 8))*INNER + h*DHEAD;
    #pragma unroll
    for (int ns = 0; ns < 4; ++ns) {
        float2 a, b;
        a.x = oc[ns][0]*inv0; a.y = oc[ns][1]*inv0;
        b.x = oc[ns][2]*inv1; b.y = oc[ns][3]*inv1;
        *(float2*)(o0 + ns*8 + 2*q) = a;
        *(float2*)(o1 + ns*8 + 2*q) = b;
    }
}

// ---------------- launch ----------------------------------------------------
extern "C" void kernel_launch(void* const* d_in, const int* in_sizes, int n_in,
                              void* d_out, int out_size)
{
    const float* x        = (const float*)d_in[0];
    const float* rel_bias = (const float*)d_in[1];
    const float* ln_scale = (const float*)d_in[2];
    const float* w_qkv    = (const float*)d_in[3];
    const float* w_out    = (const float*)d_in[4];
    const float* b_out    = (const float*)d_in[5];
    float*       out      = (float*)d_out;

    ln_kernel<<<ROWS, 128>>>(x, ln_scale);

    dim3 g1(3*INNER/64, ROWS/128);    // (12, 32)
    gemm_qkv_tc<<<g1, 256>>>(w_qkv);

    dim3 g2(NSEQ/128, BATCH*HEADS);   // (16, 16)
    attn_mma_kernel<<<g2, 256>>>(rel_bias);

    dim3 g3(DIM/64, ROWS/128);        // (8, 32)
    gemm_out_tc<<<g3, 256>>>(w_out, b_out, out);
}

// round 9
// speedup vs baseline: 1.5655x; 1.2440x over previous
#include <cuda_runtime.h>
#include <math.h>
#include <cstdint>

#define BATCH  2
#define NSEQ   2048
#define DIM    512
#define HEADS  8
#define DHEAD  32
#define INNER  256
#define ROWS   (BATCH*NSEQ)   // 4096

// ---------------- scratch (device globals: no allocation allowed) ----------
__device__ float g_xn[ROWS*DIM];
__device__ float g_q [BATCH*HEADS*NSEQ*DHEAD];   // pre-scaled by 1/sqrt(32)
__device__ float g_k [BATCH*HEADS*NSEQ*DHEAD];
__device__ float g_v [BATCH*HEADS*NSEQ*DHEAD];
__device__ float g_o [ROWS*INNER];

__device__ __forceinline__ float to_tf32(float x) {
    float r;
    asm("cvt.rna.tf32.f32 %0, %1;" : "=f"(r) : "f"(x));
    return r;
}
__device__ __forceinline__ uint32_t fau(float x) { return __float_as_uint(x); }

__device__ __forceinline__ uint32_t smem_u32(const void* p) {
    uint32_t a;
    asm("{ .reg .u64 t; cvta.to.shared.u64 t, %1; cvt.u32.u64 %0, t; }" : "=r"(a) : "l"(p));
    return a;
}
__device__ __forceinline__ void cp16(uint32_t saddr, const void* g) {
    asm volatile("cp.async.cg.shared.global [%0], [%1], 16;" :: "r"(saddr), "l"(g));
}
#define CP_COMMIT() asm volatile("cp.async.commit_group;" ::: "memory")
#define CP_WAIT(n)  asm volatile("cp.async.wait_group %0;" :: "n"(n) : "memory")

// mma.sync m16n8k8 tf32 (sm_80+ portable)
__device__ __forceinline__ void mma_tf32(float* d, const uint32_t* a,
                                         uint32_t b0, uint32_t b1) {
    asm volatile(
        "mma.sync.aligned.m16n8k8.row.col.f32.tf32.tf32.f32 "
        "{%0,%1,%2,%3}, {%4,%5,%6,%7}, {%8,%9}, {%0,%1,%2,%3};"
        : "+f"(d[0]), "+f"(d[1]), "+f"(d[2]), "+f"(d[3])
        : "r"(a[0]), "r"(a[1]), "r"(a[2]), "r"(a[3]), "r"(b0), "r"(b1));
}

// ---------------- 1) LayerNorm ---------------------------------------------
__global__ __launch_bounds__(128) void ln_kernel(const float* __restrict__ x,
                                                 const float* __restrict__ gamma)
{
    int row = blockIdx.x;
    int t   = threadIdx.x;
    const float* xr = x + (size_t)row*DIM;

    float4 xv = *(const float4*)(xr + t*4);
    float s  = xv.x + xv.y + xv.z + xv.w;
    float ss = xv.x*xv.x + xv.y*xv.y + xv.z*xv.z + xv.w*xv.w;

    #pragma unroll
    for (int ofs = 16; ofs >= 1; ofs >>= 1) {
        s  += __shfl_xor_sync(0xffffffffu, s,  ofs);
        ss += __shfl_xor_sync(0xffffffffu, ss, ofs);
    }
    __shared__ float rs[4], rss[4];
    int lane = t & 31, wid = t >> 5;
    if (lane == 0) { rs[wid] = s; rss[wid] = ss; }
    __syncthreads();
    s  = rs[0]  + rs[1]  + rs[2]  + rs[3];
    ss = rss[0] + rss[1] + rss[2] + rss[3];

    float mu   = s * (1.0f/DIM);
    float var  = ss * (1.0f/DIM) - mu*mu;
    float rstd = rsqrtf(var + 1e-5f);

    float4 g = *(const float4*)(gamma + t*4);
    float4 o;
    o.x = (xv.x - mu) * rstd * g.x;
    o.y = (xv.y - mu) * rstd * g.y;
    o.z = (xv.z - mu) * rstd * g.z;
    o.w = (xv.w - mu) * rstd * g.w;
    *(float4*)(g_xn + (size_t)row*DIM + t*4) = o;
}

// ======= split-tf32 tensor GEMM core: cp.async double-buffered (R8 WIN) =====
template<int KDIM, int NSTRIDE>
__device__ __forceinline__ void gemm_tc_core(const float* __restrict__ A,
                                             const float* __restrict__ Bm,
                                             float (*sm)[6144],
                                             float c[2][4][4])
{
    const int tid  = threadIdx.x;
    const int lane = tid & 31;
    const int w    = tid >> 5;
    const int wm   = w >> 1, wn = w & 1;
    const int g    = lane >> 2, q = lane & 3;
    const int bm   = blockIdx.y * 128;
    const int bn   = blockIdx.x * 64;
    const int KT   = KDIM / 32;

    const int ar  = tid >> 3;
    const int ac4 = tid & 7;
    const int br  = tid >> 4;
    const int bc4 = tid & 15;

    uint32_t sbase[2] = { smem_u32(&sm[0][0]), smem_u32(&sm[1][0]) };

    {
        #pragma unroll
        for (int u = 0; u < 4; ++u) {
            int row = u*32 + ar;
            int sc4 = ac4 ^ (row & 7);
            cp16(sbase[0] + (uint32_t)(row*8 + sc4)*16,
                 A + (size_t)(bm+row)*KDIM + ac4*4);
        }
        #pragma unroll
        for (int u = 0; u < 2; ++u) {
            int k   = u*16 + br;
            int sc4 = bc4 ^ ((k & 3) << 1);
            cp16(sbase[0] + 16384u + (uint32_t)(k*16 + sc4)*16,
                 Bm + (size_t)k*NSTRIDE + bn + bc4*4);
        }
        CP_COMMIT();
    }

    for (int t = 0; t < KT; ++t) {
        if (t + 1 < KT) {
            int kt = (t+1) * 32;
            uint32_t sb = sbase[(t+1) & 1];
            #pragma unroll
            for (int u = 0; u < 4; ++u) {
                int row = u*32 + ar;
                int sc4 = ac4 ^ (row & 7);
                cp16(sb + (uint32_t)(row*8 + sc4)*16,
                     A + (size_t)(bm+row)*KDIM + kt + ac4*4);
            }
            #pragma unroll
            for (int u = 0; u < 2; ++u) {
                int k   = u*16 + br;
                int sc4 = bc4 ^ ((k & 3) << 1);
                cp16(sb + 16384u + (uint32_t)(k*16 + sc4)*16,
                     Bm + (size_t)(kt+k)*NSTRIDE + bn + bc4*4);
            }
            CP_COMMIT();
            CP_WAIT(1);
        } else {
            CP_WAIT(0);
        }
        __syncthreads();

        const float* sA = &sm[t & 1][0];
        const float* sB = &sm[t & 1][4096];

        #pragma unroll
        for (int ks = 0; ks < 4; ++ks) {
            uint32_t ah[2][4], al[2][4];
            #pragma unroll
            for (int i = 0; i < 2; ++i) {
                #pragma unroll
                for (int r = 0; r < 4; ++r) {
                    int row = wm*32 + i*16 + g + 8*(r & 1);
                    int c4  = (ks*2 + (r >> 1)) ^ (row & 7);
                    float v = sA[row*32 + c4*4 + q];
                    float h = to_tf32(v);
                    ah[i][r] = fau(h);
                    al[i][r] = fau(to_tf32(v - h));
                }
            }
            uint32_t bh[4][2], bl[4][2];
            #pragma unroll
            for (int j = 0; j < 4; ++j) {
                #pragma unroll
                for (int r = 0; r < 2; ++r) {
                    int k  = ks*8 + q + 4*r;
                    int n  = wn*32 + j*8 + g;
                    int c4 = (n >> 2) ^ ((k & 3) << 1);
                    float v = sB[k*64 + c4*4 + (n & 3)];
                    float h = to_tf32(v);
                    bh[j][r] = fau(h);
                    bl[j][r] = fau(to_tf32(v - h));
                }
            }
            #pragma unroll
            for (int i = 0; i < 2; ++i)
                #pragma unroll
                for (int j = 0; j < 4; ++j) {
                    mma_tf32(c[i][j], ah[i], bh[j][0], bh[j][1]);
                    mma_tf32(c[i][j], ah[i], bl[j][0], bl[j][1]);
                    mma_tf32(c[i][j], al[i], bh[j][0], bh[j][1]);
                }
        }
        __syncthreads();
    }
}

// ---------------- 2) QKV GEMM via pipelined split tf32 mma -------------------
__global__ __launch_bounds__(256) void gemm_qkv_tc(const float* __restrict__ B)
{
    __shared__ float sm[2][6144];
    float c[2][4][4] = {};
    gemm_tc_core<DIM, 3*INNER>(g_xn, B, sm, c);

    int tid  = threadIdx.x;
    int lane = tid & 31;
    int w    = tid >> 5;
    int wm   = w >> 1, wn = w & 1;
    int g    = lane >> 2, q = lane & 3;
    int bm   = blockIdx.y * 128;
    int bn   = blockIdx.x * 64;

    #pragma unroll
    for (int i = 0; i < 2; ++i) {
        int row0 = bm + wm*32 + i*16 + g;
        #pragma unroll
        for (int j = 0; j < 4; ++j) {
            int col  = bn + wn*32 + j*8 + 2*q;
            int part = col >> 8;
            int rest = col & 255;
            int h    = rest >> 5;
            int d    = rest & 31;
            float* dst = (part == 0) ? g_q : (part == 1) ? g_k : g_v;
            float scl  = (part == 0) ? 0.17677669529663687f : 1.0f;
            #pragma unroll
            for (int r = 0; r < 2; ++r) {
                int rm = row0 + r*8;
                int b_ = rm >> 11;
                int n  = rm & 2047;
                float2 o;
                o.x = c[i][j][r*2+0] * scl;
                o.y = c[i][j][r*2+1] * scl;
                *(float2*)(dst + ((size_t)((b_*HEADS + h)*NSEQ + n))*DHEAD + d) = o;
            }
        }
    }
}

// ---------------- 4) Out projection via pipelined split tf32 mma -------------
__global__ __launch_bounds__(256) void gemm_out_tc(const float* __restrict__ B,
                                                   const float* __restrict__ bvec,
                                                   float* __restrict__ out)
{
    __shared__ float sm[2][6144];
    float c[2][4][4] = {};
    gemm_tc_core<INNER, DIM>(g_o, B, sm, c);

    int tid  = threadIdx.x;
    int lane = tid & 31;
    int w    = tid >> 5;
    int wm   = w >> 1, wn = w & 1;
    int g    = lane >> 2, q = lane & 3;
    int bm   = blockIdx.y * 128;
    int bn   = blockIdx.x * 64;

    #pragma unroll
    for (int i = 0; i < 2; ++i) {
        int row0 = bm + wm*32 + i*16 + g;
        #pragma unroll
        for (int j = 0; j < 4; ++j) {
            int col = bn + wn*32 + j*8 + 2*q;
            float2 bb = *(const float2*)(bvec + col);
            #pragma unroll
            for (int r = 0; r < 2; ++r) {
                int rm = row0 + r*8;
                float2 o;
                o.x = c[i][j][r*2+0] + bb.x;
                o.y = c[i][j][r*2+1] + bb.y;
                *(float2*)(out + (size_t)rm*DIM + col) = o;
            }
        }
    }
}

// ---------------- 3) Attention: cp.async pipelined tf32 mma ------------------
// grid (16 i-tiles of 128, 16 bh), 256 thr = 8 warps. j-tiles of 64, NT=32.
// Dynamic smem (floats):
//   [    0.. 4096)  K/V stage 0:  K 64x32 swz (c4^=row&7), V 64x32 swz (c4^=(row&3)<<1)
//   [ 4096.. 8192)  K/V stage 1
//   [ 8192..16384)  bias stage 0: 128x16 float4, swz c4^=row&15
//   [16384..24576)  bias stage 1  (also Q staging scratch before the loop)
#define ATT_SMEM_BYTES (24576*4)

__global__ __launch_bounds__(256) void attn_mma_kernel(const float* __restrict__ bias)
{
    extern __shared__ float smem[];

    int tid  = threadIdx.x;
    int w    = tid >> 5;
    int lane = tid & 31;
    int g    = lane >> 2;
    int q    = lane & 3;
    int bh   = blockIdx.y;
    int i0   = blockIdx.x * 128;
    int h    = bh & 7;
    int b_   = bh >> 3;

    const float* qb = g_q + (size_t)bh*NSEQ*DHEAD;
    const float* kb = g_k + (size_t)bh*NSEQ*DHEAD;
    const float* vb = g_v + (size_t)bh*NSEQ*DHEAD;
    const float* bp = bias + (size_t)h*NSEQ*NSEQ + (size_t)i0*NSEQ;  // [128][2048]

    // ---- stage Q in bias-stage-1 area, extract a-frags ----
    {
        float* qs = smem + 16384;
        #pragma unroll
        for (int u = 0; u < 4; ++u) {
            int f   = u*256 + tid;
            int row = f >> 3;
            int dg  = (f & 7) * 4;
            float4 qv = *(const float4*)(qb + (size_t)(i0+row)*DHEAD + dg);
            float* s  = &qs[row*33 + dg];
            s[0] = qv.x; s[1] = qv.y; s[2] = qv.z; s[3] = qv.w;
        }
    }
    __syncthreads();

    uint32_t qa[4][4];
    {
        const float* qs = smem + 16384;
        int r0 = w*16 + g;
        #pragma unroll
        for (int ks = 0; ks < 4; ++ks) {
            qa[ks][0] = fau(to_tf32(qs[(r0  )*33 + ks*8 + q    ]));
            qa[ks][1] = fau(to_tf32(qs[(r0+8)*33 + ks*8 + q    ]));
            qa[ks][2] = fau(to_tf32(qs[(r0  )*33 + ks*8 + q + 4]));
            qa[ks][3] = fau(to_tf32(qs[(r0+8)*33 + ks*8 + q + 4]));
        }
    }
    __syncthreads();

    uint32_t s_kv[2] = { smem_u32(smem), smem_u32(smem + 4096) };
    uint32_t s_bi[2] = { smem_u32(smem + 8192), smem_u32(smem + 16384) };

    // prefetch helper (inlined twice via lambda-ish macro)
    #define PREFETCH_TILE(stg, JT)                                                 \
    do {                                                                           \
        _Pragma("unroll")                                                          \
        for (int u = 0; u < 2; ++u) {                                              \
            int f   = u*256 + tid;                                                 \
            int row = f >> 3;                                                      \
            int c4  = f & 7;                                                       \
            cp16(s_kv[stg] + (uint32_t)((row*8 + (c4 ^ (row & 7))) << 4),          \
                 kb + (size_t)((JT)+row)*DHEAD + c4*4);                            \
            cp16(s_kv[stg] + 8192u + (uint32_t)((row*8 + (c4 ^ ((row & 3) << 1))) << 4), \
                 vb + (size_t)((JT)+row)*DHEAD + c4*4);                            \
        }                                                                          \
        _Pragma("unroll")                                                          \
        for (int u = 0; u < 8; ++u) {                                              \
            int f   = u*256 + tid;                                                 \
            int row = f >> 4;                                                      \
            int c4  = f & 15;                                                      \
            cp16(s_bi[stg] + (uint32_t)((row*16 + (c4 ^ (row & 15))) << 4),        \
                 bp + (size_t)row*NSEQ + (JT) + c4*4);                             \
        }                                                                          \
        CP_COMMIT();                                                               \
    } while (0)

    PREFETCH_TILE(0, 0);

    float oc[4][4] = {};
    float lsum0 = 0.f, lsum1 = 0.f;
    const int r0l = w*16 + g;

    for (int it = 0; it < 32; ++it) {
        if (it + 1 < 32) {
            PREFETCH_TILE((it+1) & 1, (it+1)*64);
            CP_WAIT(1);
        } else {
            CP_WAIT(0);
        }
        __syncthreads();

        const float* Ks = smem + (it & 1)*4096;
        const float* Vs = Ks + 2048;
        const float* Bs = smem + 8192 + (it & 1)*8192;

        // ---- S = Q K^T ----
        float c[8][4] = {};
        #pragma unroll
        for (int js = 0; js < 8; ++js) {
            #pragma unroll
            for (int ks = 0; ks < 4; ++ks) {
                uint32_t b0, b1;
                #pragma unroll
                for (int r = 0; r < 2; ++r) {
                    float v = Ks[(js*8 + g)*32 + (((ks*2 + r) ^ g) << 2) + q];
                    if (r == 0) b0 = fau(to_tf32(v)); else b1 = fau(to_tf32(v));
                }
                mma_tf32(c[js], qa[ks], b0, b1);
            }
        }

        // ---- softmax: bias from smem (prefetched), exp, row sums ----
        #pragma unroll
        for (int s = 0; s < 8; ++s) {
            int c4l = s*2 + (q >> 1);
            int e   = 2*(q & 1);
            float2 bv0 = *(const float2*)&Bs[(r0l  )*64 + ((c4l ^ ( r0l      & 15)) << 2) + e];
            float2 bv1 = *(const float2*)&Bs[(r0l+8)*64 + ((c4l ^ ((r0l + 8) & 15)) << 2) + e];
            float p0 = __expf(c[s][0] + bv0.x);
            float p1 = __expf(c[s][1] + bv0.y);
            float p2 = __expf(c[s][2] + bv1.x);
            float p3 = __expf(c[s][3] + bv1.y);
            lsum0 += p0 + p1;
            lsum1 += p2 + p3;
            c[s][0] = to_tf32(p0); c[s][1] = to_tf32(p1);
            c[s][2] = to_tf32(p2); c[s][3] = to_tf32(p3);
        }

        // ---- O += P V : c-frag -> a-frag via quad shuffles ----
        #pragma unroll
        for (int ks = 0; ks < 8; ++ks) {
            int src0 = (lane & ~3) | (q >> 1);
            int src1 = src0 + 2;
            float t0 = __shfl_sync(0xffffffffu, c[ks][0], src0);
            float t1 = __shfl_sync(0xffffffffu, c[ks][1], src0);
            float t2 = __shfl_sync(0xffffffffu, c[ks][2], src0);
            float t3 = __shfl_sync(0xffffffffu, c[ks][3], src0);
            float u0 = __shfl_sync(0xffffffffu, c[ks][0], src1);
            float u1 = __shfl_sync(0xffffffffu, c[ks][1], src1);
            float u2 = __shfl_sync(0xffffffffu, c[ks][2], src1);
            float u3 = __shfl_sync(0xffffffffu, c[ks][3], src1);
            bool odd = (q & 1);
            uint32_t pa[4];
            pa[0] = fau(odd ? t1 : t0);
            pa[1] = fau(odd ? t3 : t2);
            pa[2] = fau(odd ? u1 : u0);
            pa[3] = fau(odd ? u3 : u2);
            #pragma unroll
            for (int ns = 0; ns < 4; ++ns) {
                uint32_t b0, b1;
                #pragma unroll
                for (int r = 0; r < 2; ++r) {
                    int j = ks*8 + q + 4*r;
                    float v = Vs[j*32 + (((ns*2 + (g >> 2)) ^ (q << 1)) << 2) + (g & 3)];
                    if (r == 0) b0 = fau(to_tf32(v)); else b1 = fau(to_tf32(v));
                }
                mma_tf32(oc[ns], pa, b0, b1);
            }
        }
        __syncthreads();
    }

    // ---- finalize: reduce l over quad, normalize, store ----
    #pragma unroll
    for (int ofs = 1; ofs <= 2; ofs <<= 1) {
        lsum0 += __shfl_xor_sync(0xffffffffu, lsum0, ofs);
        lsum1 += __shfl_xor_sync(0xffffffffu, lsum1, ofs);
    }
    float inv0 = 1.0f / lsum0;
    float inv1 = 1.0f / lsum1;

    int r0 = i0 + w*16 + g;
    float* o0 = g_o + ((size_t)(b_*NSEQ + r0    ))*INNER + h*DHEAD;
    float* o1 = g_o + ((size_t)(b_*NSEQ + r0 + 8))*INNER + h*DHEAD;
    #pragma unroll
    for (int ns = 0; ns < 4; ++ns) {
        float2 a, b;
        a.x = oc[ns][0]*inv0; a.y = oc[ns][1]*inv0;
        b.x = oc[ns][2]*inv1; b.y = oc[ns][3]*inv1;
        *(float2*)(o0 + ns*8 + 2*q) = a;
        *(float2*)(o1 + ns*8 + 2*q) = b;
    }
}

// ---------------- launch ----------------------------------------------------
extern "C" void kernel_launch(void* const* d_in, const int* in_sizes, int n_in,
                              void* d_out, int out_size)
{
    const float* x        = (const float*)d_in[0];
    const float* rel_bias = (const float*)d_in[1];
    const float* ln_scale = (const float*)d_in[2];
    const float* w_qkv    = (const float*)d_in[3];
    const float* w_out    = (const float*)d_in[4];
    const float* b_out    = (const float*)d_in[5];
    float*       out      = (float*)d_out;

    ln_kernel<<<ROWS, 128>>>(x, ln_scale);

    dim3 g1(3*INNER/64, ROWS/128);    // (12, 32)
    gemm_qkv_tc<<<g1, 256>>>(w_qkv);

    static int att_attr_set = 0;
    if (!att_attr_set) {
        cudaFuncSetAttribute(attn_mma_kernel,
                             cudaFuncAttributeMaxDynamicSharedMemorySize,
                             ATT_SMEM_BYTES);
        att_attr_set = 1;
    }
    dim3 g2(NSEQ/128, BATCH*HEADS);   // (16, 16)
    attn_mma_kernel<<<g2, 256, ATT_SMEM_BYTES>>>(rel_bias);

    dim3 g3(DIM/64, ROWS/128);        // (8, 32)
    gemm_out_tc<<<g3, 256>>>(w_out, b_out, out);
}

// round 10
// speedup vs baseline: 1.9370x; 1.2374x over previous
#include <cuda_runtime.h>
#include <math.h>
#include <cstdint>

#define BATCH  2
#define NSEQ   2048
#define DIM    512
#define HEADS  8
#define DHEAD  32
#define INNER  256
#define ROWS   (BATCH*NSEQ)   // 4096

// ---------------- scratch (device globals: no allocation allowed) ----------
// packed bf16x2 hi/lo operand tensors (pairs along the k dimension)
__device__ uint32_t g_xn_h[ROWS*DIM/2], g_xn_l[ROWS*DIM/2];          // LN out
__device__ uint32_t g_w1h[(DIM/2)*(3*INNER)], g_w1l[(DIM/2)*(3*INNER)];
__device__ uint32_t g_oh[ROWS*INNER/2],  g_ol[ROWS*INNER/2];         // attn out
__device__ uint32_t g_w2h[(INNER/2)*DIM], g_w2l[(INNER/2)*DIM];
__device__ float g_q[BATCH*HEADS*NSEQ*DHEAD];    // pre-scaled by 1/sqrt(32)
__device__ float g_k[BATCH*HEADS*NSEQ*DHEAD];
__device__ float g_v[BATCH*HEADS*NSEQ*DHEAD];

__device__ __forceinline__ float to_tf32(float x) {
    float r;
    asm("cvt.rna.tf32.f32 %0, %1;" : "=f"(r) : "f"(x));
    return r;
}
__device__ __forceinline__ uint32_t fau(float x) { return __float_as_uint(x); }

// pack two f32 -> bf16x2 (hiF in upper half, loF in lower half)
#define PACK2(dst, hiF, loF) \
    asm("cvt.rn.bf16x2.f32 %0, %1, %2;" : "=r"(dst) : "f"(hiF), "f"(loF))
__device__ __forceinline__ float bflo(uint32_t p) { return __uint_as_float(p << 16); }
__device__ __forceinline__ float bfhi(uint32_t p) { return __uint_as_float(p & 0xffff0000u); }

__device__ __forceinline__ uint32_t smem_u32(const void* p) {
    uint32_t a;
    asm("{ .reg .u64 t; cvta.to.shared.u64 t, %1; cvt.u32.u64 %0, t; }" : "=r"(a) : "l"(p));
    return a;
}
__device__ __forceinline__ void cp16(uint32_t saddr, const void* g) {
    asm volatile("cp.async.cg.shared.global [%0], [%1], 16;" :: "r"(saddr), "l"(g));
}
#define CP_COMMIT() asm volatile("cp.async.commit_group;" ::: "memory")
#define CP_WAIT(n)  asm volatile("cp.async.wait_group %0;" :: "n"(n) : "memory")

// mma m16n8k8 tf32 (attention, proven)
__device__ __forceinline__ void mma_tf32(float* d, const uint32_t* a,
                                         uint32_t b0, uint32_t b1) {
    asm volatile(
        "mma.sync.aligned.m16n8k8.row.col.f32.tf32.tf32.f32 "
        "{%0,%1,%2,%3}, {%4,%5,%6,%7}, {%8,%9}, {%0,%1,%2,%3};"
        : "+f"(d[0]), "+f"(d[1]), "+f"(d[2]), "+f"(d[3])
        : "r"(a[0]), "r"(a[1]), "r"(a[2]), "r"(a[3]), "r"(b0), "r"(b1));
}
// mma m16n8k16 bf16 (GEMMs)
__device__ __forceinline__ void mma_bf16(float* d, const uint32_t* a, const uint32_t* b) {
    asm volatile(
        "mma.sync.aligned.m16n8k16.row.col.f32.bf16.bf16.f32 "
        "{%0,%1,%2,%3}, {%4,%5,%6,%7}, {%8,%9}, {%0,%1,%2,%3};"
        : "+f"(d[0]), "+f"(d[1]), "+f"(d[2]), "+f"(d[3])
        : "r"(a[0]), "r"(a[1]), "r"(a[2]), "r"(a[3]), "r"(b[0]), "r"(b[1]));
}

// ---------------- 0) weight pack: f32 [K][N] -> bf16x2 h/l [K/2][N] ---------
__global__ __launch_bounds__(256) void pack_w_kernel(const float* __restrict__ w,
                                                     uint32_t* __restrict__ wh,
                                                     uint32_t* __restrict__ wl,
                                                     int N, int total)
{
    int idx = blockIdx.x*256 + threadIdx.x;
    if (idx >= total) return;
    int kp = idx / N;
    int n  = idx - kp*N;
    float v0 = w[(size_t)(2*kp  )*N + n];
    float v1 = w[(size_t)(2*kp+1)*N + n];
    uint32_t ph, pl;
    PACK2(ph, v1, v0);
    PACK2(pl, v1 - bfhi(ph), v0 - bflo(ph));
    wh[idx] = ph; wl[idx] = pl;
}

// ---------------- 1) LayerNorm (writes packed bf16x2 h/l) -------------------
__global__ __launch_bounds__(128) void ln_kernel(const float* __restrict__ x,
                                                 const float* __restrict__ gamma)
{
    int row = blockIdx.x;
    int t   = threadIdx.x;
    const float* xr = x + (size_t)row*DIM;

    float4 xv = *(const float4*)(xr + t*4);
    float s  = xv.x + xv.y + xv.z + xv.w;
    float ss = xv.x*xv.x + xv.y*xv.y + xv.z*xv.z + xv.w*xv.w;

    #pragma unroll
    for (int ofs = 16; ofs >= 1; ofs >>= 1) {
        s  += __shfl_xor_sync(0xffffffffu, s,  ofs);
        ss += __shfl_xor_sync(0xffffffffu, ss, ofs);
    }
    __shared__ float rs[4], rss[4];
    int lane = t & 31, wid = t >> 5;
    if (lane == 0) { rs[wid] = s; rss[wid] = ss; }
    __syncthreads();
    s  = rs[0]  + rs[1]  + rs[2]  + rs[3];
    ss = rss[0] + rss[1] + rss[2] + rss[3];

    float mu   = s * (1.0f/DIM);
    float var  = ss * (1.0f/DIM) - mu*mu;
    float rstd = rsqrtf(var + 1e-5f);

    float4 g = *(const float4*)(gamma + t*4);
    float4 o;
    o.x = (xv.x - mu) * rstd * g.x;
    o.y = (xv.y - mu) * rstd * g.y;
    o.z = (xv.z - mu) * rstd * g.z;
    o.w = (xv.w - mu) * rstd * g.w;

    uint32_t h0, h1, l0, l1;
    PACK2(h0, o.y, o.x);
    PACK2(h1, o.w, o.z);
    PACK2(l0, o.y - bfhi(h0), o.x - bflo(h0));
    PACK2(l1, o.w - bfhi(h1), o.z - bflo(h1));
    *(uint2*)&g_xn_h[(size_t)row*256 + 2*t] = make_uint2(h0, h1);
    *(uint2*)&g_xn_l[(size_t)row*256 + 2*t] = make_uint2(l0, l1);
}

// ====== bf16x2-split tensor GEMM core: cp.async double-buffered =============
// Block 128x64, BK=32 (=16 pairs), 256 thr = 8 warps (wm 0..3, wn 0..1).
// Stage (uint32 units, 6144 total): Ah[128][16] @0, Al @2048, Bh[16][64] @4096, Bl @5120
// A swizzle: c4 ^= (row>>1)&3 ; B swizzle: c4 ^= (kp&3)<<1  (bank-verified)
template<int KP, int NSTRIDE>
__device__ __forceinline__ void gemm_bf16_core(
    const uint32_t* __restrict__ Ah, const uint32_t* __restrict__ Al,
    const uint32_t* __restrict__ Bh, const uint32_t* __restrict__ Bl,
    uint32_t (*sm)[6144], float c[2][4][4])
{
    const int tid  = threadIdx.x;
    const int lane = tid & 31;
    const int w    = tid >> 5;
    const int wm   = w >> 1, wn = w & 1;
    const int g    = lane >> 2, q = lane & 3;
    const int bm   = blockIdx.y * 128;
    const int bn   = blockIdx.x * 64;
    const int KT   = KP / 16;

    const int arow = tid >> 2, ac4 = tid & 3;
    const int brow = tid >> 4, bc4 = tid & 15;
    const uint32_t aswz0 = (uint32_t)(ac4 ^ ((arow      >> 1) & 3));
    const uint32_t aswz1 = (uint32_t)(ac4 ^ (((arow+64) >> 1) & 3));
    const uint32_t bswz  = (uint32_t)(bc4 ^ ((brow & 3) << 1));

    uint32_t sbase[2] = { smem_u32(&sm[0][0]), smem_u32(&sm[1][0]) };

    #define GPREF(SB, T)                                                        \
    do {                                                                        \
        cp16((SB) + (uint32_t)arow*64u + aswz0*16u,                             \
             Ah + (size_t)(bm+arow)*KP + (T)*16 + ac4*4);                       \
        cp16((SB) + (uint32_t)(arow+64)*64u + aswz1*16u,                        \
             Ah + (size_t)(bm+arow+64)*KP + (T)*16 + ac4*4);                    \
        cp16((SB) + 8192u + (uint32_t)arow*64u + aswz0*16u,                     \
             Al + (size_t)(bm+arow)*KP + (T)*16 + ac4*4);                       \
        cp16((SB) + 8192u + (uint32_t)(arow+64)*64u + aswz1*16u,                \
             Al + (size_t)(bm+arow+64)*KP + (T)*16 + ac4*4);                    \
        cp16((SB) + 16384u + (uint32_t)brow*256u + bswz*16u,                    \
             Bh + (size_t)((T)*16+brow)*NSTRIDE + bn + bc4*4);                  \
        cp16((SB) + 20480u + (uint32_t)brow*256u + bswz*16u,                    \
             Bl + (size_t)((T)*16+brow)*NSTRIDE + bn + bc4*4);                  \
        CP_COMMIT();                                                            \
    } while (0)

    GPREF(sbase[0], 0);

    for (int t = 0; t < KT; ++t) {
        if (t + 1 < KT) { GPREF(sbase[(t+1) & 1], t+1); CP_WAIT(1); }
        else            { CP_WAIT(0); }
        __syncthreads();

        const uint32_t* sAh = &sm[t & 1][0];
        const uint32_t* sAl = sAh + 2048;
        const uint32_t* sBh = sAh + 4096;
        const uint32_t* sBl = sAh + 5120;

        #pragma unroll
        for (int ks = 0; ks < 2; ++ks) {
            uint32_t ah[2][4], al[2][4];
            #pragma unroll
            for (int i = 0; i < 2; ++i) {
                #pragma unroll
                for (int r = 0; r < 4; ++r) {
                    int row = wm*32 + i*16 + g + 8*(r & 1);
                    int c4  = (ks*2 + (r >> 1)) ^ ((g >> 1) & 3);
                    int idx = row*16 + c4*4 + q;
                    ah[i][r] = sAh[idx];
                    al[i][r] = sAl[idx];
                }
            }
            uint32_t bh[4][2], bl[4][2];
            #pragma unroll
            for (int j = 0; j < 4; ++j) {
                #pragma unroll
                for (int r = 0; r < 2; ++r) {
                    int kp = ks*8 + q + 4*r;
                    int n  = wn*32 + j*8 + g;
                    int c4 = (n >> 2) ^ ((kp & 3) << 1);
                    int idx = kp*64 + c4*4 + (n & 3);
                    bh[j][r] = sBh[idx];
                    bl[j][r] = sBl[idx];
                }
            }
            #pragma unroll
            for (int i = 0; i < 2; ++i)
                #pragma unroll
                for (int j = 0; j < 4; ++j) {
                    mma_bf16(c[i][j], ah[i], bh[j]);
                    mma_bf16(c[i][j], ah[i], bl[j]);
                    mma_bf16(c[i][j], al[i], bh[j]);
                }
        }
        __syncthreads();
    }
    #undef GPREF
}

// ---------------- 2) QKV GEMM (bf16x2 split) --------------------------------
__global__ __launch_bounds__(256) void gemm_qkv_tc()
{
    __shared__ uint32_t sm[2][6144];
    float c[2][4][4] = {};
    gemm_bf16_core<DIM/2, 3*INNER>(g_xn_h, g_xn_l, g_w1h, g_w1l, sm, c);

    int tid  = threadIdx.x;
    int lane = tid & 31;
    int w    = tid >> 5;
    int wm   = w >> 1, wn = w & 1;
    int g    = lane >> 2, q = lane & 3;
    int bm   = blockIdx.y * 128;
    int bn   = blockIdx.x * 64;

    #pragma unroll
    for (int i = 0; i < 2; ++i) {
        int row0 = bm + wm*32 + i*16 + g;
        #pragma unroll
        for (int j = 0; j < 4; ++j) {
            int col  = bn + wn*32 + j*8 + 2*q;
            int part = col >> 8;
            int rest = col & 255;
            int h    = rest >> 5;
            int d    = rest & 31;
            float* dst = (part == 0) ? g_q : (part == 1) ? g_k : g_v;
            float scl  = (part == 0) ? 0.17677669529663687f : 1.0f;
            #pragma unroll
            for (int r = 0; r < 2; ++r) {
                int rm = row0 + r*8;
                int b_ = rm >> 11;
                int n  = rm & 2047;
                float2 o;
                o.x = c[i][j][r*2+0] * scl;
                o.y = c[i][j][r*2+1] * scl;
                *(float2*)(dst + ((size_t)((b_*HEADS + h)*NSEQ + n))*DHEAD + d) = o;
            }
        }
    }
}

// ---------------- 4) Out projection (bf16x2 split) --------------------------
__global__ __launch_bounds__(256) void gemm_out_tc(const float* __restrict__ bvec,
                                                   float* __restrict__ out)
{
    __shared__ uint32_t sm[2][6144];
    float c[2][4][4] = {};
    gemm_bf16_core<INNER/2, DIM>(g_oh, g_ol, g_w2h, g_w2l, sm, c);

    int tid  = threadIdx.x;
    int lane = tid & 31;
    int w    = tid >> 5;
    int wm   = w >> 1, wn = w & 1;
    int g    = lane >> 2, q = lane & 3;
    int bm   = blockIdx.y * 128;
    int bn   = blockIdx.x * 64;

    #pragma unroll
    for (int i = 0; i < 2; ++i) {
        int row0 = bm + wm*32 + i*16 + g;
        #pragma unroll
        for (int j = 0; j < 4; ++j) {
            int col = bn + wn*32 + j*8 + 2*q;
            float2 bb = *(const float2*)(bvec + col);
            #pragma unroll
            for (int r = 0; r < 2; ++r) {
                int rm = row0 + r*8;
                float2 o;
                o.x = c[i][j][r*2+0] + bb.x;
                o.y = c[i][j][r*2+1] + bb.y;
                *(float2*)(out + (size_t)rm*DIM + col) = o;
            }
        }
    }
}

// ---------------- 3) Attention: cp.async pipelined tf32 mma (R9 WIN) --------
#define ATT_SMEM_BYTES (24576*4)

__global__ __launch_bounds__(256) void attn_mma_kernel(const float* __restrict__ bias)
{
    extern __shared__ float smem[];

    int tid  = threadIdx.x;
    int w    = tid >> 5;
    int lane = tid & 31;
    int g    = lane >> 2;
    int q    = lane & 3;
    int bh   = blockIdx.y;
    int i0   = blockIdx.x * 128;
    int h    = bh & 7;
    int b_   = bh >> 3;

    const float* qb = g_q + (size_t)bh*NSEQ*DHEAD;
    const float* kb = g_k + (size_t)bh*NSEQ*DHEAD;
    const float* vb = g_v + (size_t)bh*NSEQ*DHEAD;
    const float* bp = bias + (size_t)h*NSEQ*NSEQ + (size_t)i0*NSEQ;

    {
        float* qs = smem + 16384;
        #pragma unroll
        for (int u = 0; u < 4; ++u) {
            int f   = u*256 + tid;
            int row = f >> 3;
            int dg  = (f & 7) * 4;
            float4 qv = *(const float4*)(qb + (size_t)(i0+row)*DHEAD + dg);
            float* s  = &qs[row*33 + dg];
            s[0] = qv.x; s[1] = qv.y; s[2] = qv.z; s[3] = qv.w;
        }
    }
    __syncthreads();

    uint32_t qa[4][4];
    {
        const float* qs = smem + 16384;
        int r0 = w*16 + g;
        #pragma unroll
        for (int ks = 0; ks < 4; ++ks) {
            qa[ks][0] = fau(to_tf32(qs[(r0  )*33 + ks*8 + q    ]));
            qa[ks][1] = fau(to_tf32(qs[(r0+8)*33 + ks*8 + q    ]));
            qa[ks][2] = fau(to_tf32(qs[(r0  )*33 + ks*8 + q + 4]));
            qa[ks][3] = fau(to_tf32(qs[(r0+8)*33 + ks*8 + q + 4]));
        }
    }
    __syncthreads();

    uint32_t s_kv[2] = { smem_u32(smem), smem_u32(smem + 4096) };
    uint32_t s_bi[2] = { smem_u32(smem + 8192), smem_u32(smem + 16384) };

    #define PREFETCH_TILE(stg, JT)                                                 \
    do {                                                                           \
        _Pragma("unroll")                                                          \
        for (int u = 0; u < 2; ++u) {                                              \
            int f   = u*256 + tid;                                                 \
            int row = f >> 3;                                                      \
            int c4  = f & 7;                                                       \
            cp16(s_kv[stg] + (uint32_t)((row*8 + (c4 ^ (row & 7))) << 4),          \
                 kb + (size_t)((JT)+row)*DHEAD + c4*4);                            \
            cp16(s_kv[stg] + 8192u + (uint32_t)((row*8 + (c4 ^ ((row & 3) << 1))) << 4), \
                 vb + (size_t)((JT)+row)*DHEAD + c4*4);                            \
        }                                                                          \
        _Pragma("unroll")                                                          \
        for (int u = 0; u < 8; ++u) {                                              \
            int f   = u*256 + tid;                                                 \
            int row = f >> 4;                                                      \
            int c4  = f & 15;                                                      \
            cp16(s_bi[stg] + (uint32_t)((row*16 + (c4 ^ (row & 15))) << 4),        \
                 bp + (size_t)row*NSEQ + (JT) + c4*4);                             \
        }                                                                          \
        CP_COMMIT();                                                               \
    } while (0)

    PREFETCH_TILE(0, 0);

    float oc[4][4] = {};
    float lsum0 = 0.f, lsum1 = 0.f;
    const int r0l = w*16 + g;

    for (int it = 0; it < 32; ++it) {
        if (it + 1 < 32) {
            PREFETCH_TILE((it+1) & 1, (it+1)*64);
            CP_WAIT(1);
        } else {
            CP_WAIT(0);
        }
        __syncthreads();

        const float* Ks = smem + (it & 1)*4096;
        const float* Vs = Ks + 2048;
        const float* Bs = smem + 8192 + (it & 1)*8192;

        float c[8][4] = {};
        #pragma unroll
        for (int js = 0; js < 8; ++js) {
            #pragma unroll
            for (int ks = 0; ks < 4; ++ks) {
                uint32_t b0, b1;
                #pragma unroll
                for (int r = 0; r < 2; ++r) {
                    float v = Ks[(js*8 + g)*32 + (((ks*2 + r) ^ g) << 2) + q];
                    if (r == 0) b0 = fau(to_tf32(v)); else b1 = fau(to_tf32(v));
                }
                mma_tf32(c[js], qa[ks], b0, b1);
            }
        }

        #pragma unroll
        for (int s = 0; s < 8; ++s) {
            int c4l = s*2 + (q >> 1);
            int e   = 2*(q & 1);
            float2 bv0 = *(const float2*)&Bs[(r0l  )*64 + ((c4l ^ ( r0l      & 15)) << 2) + e];
            float2 bv1 = *(const float2*)&Bs[(r0l+8)*64 + ((c4l ^ ((r0l + 8) & 15)) << 2) + e];
            float p0 = __expf(c[s][0] + bv0.x);
            float p1 = __expf(c[s][1] + bv0.y);
            float p2 = __expf(c[s][2] + bv1.x);
            float p3 = __expf(c[s][3] + bv1.y);
            lsum0 += p0 + p1;
            lsum1 += p2 + p3;
            c[s][0] = to_tf32(p0); c[s][1] = to_tf32(p1);
            c[s][2] = to_tf32(p2); c[s][3] = to_tf32(p3);
        }

        #pragma unroll
        for (int ks = 0; ks < 8; ++ks) {
            int src0 = (lane & ~3) | (q >> 1);
            int src1 = src0 + 2;
            float t0 = __shfl_sync(0xffffffffu, c[ks][0], src0);
            float t1 = __shfl_sync(0xffffffffu, c[ks][1], src0);
            float t2 = __shfl_sync(0xffffffffu, c[ks][2], src0);
            float t3 = __shfl_sync(0xffffffffu, c[ks][3], src0);
            float u0 = __shfl_sync(0xffffffffu, c[ks][0], src1);
            float u1 = __shfl_sync(0xffffffffu, c[ks][1], src1);
            float u2 = __shfl_sync(0xffffffffu, c[ks][2], src1);
            float u3 = __shfl_sync(0xffffffffu, c[ks][3], src1);
            bool odd = (q & 1);
            uint32_t pa[4];
            pa[0] = fau(odd ? t1 : t0);
            pa[1] = fau(odd ? t3 : t2);
            pa[2] = fau(odd ? u1 : u0);
            pa[3] = fau(odd ? u3 : u2);
            #pragma unroll
            for (int ns = 0; ns < 4; ++ns) {
                uint32_t b0, b1;
                #pragma unroll
                for (int r = 0; r < 2; ++r) {
                    int j = ks*8 + q + 4*r;
                    float v = Vs[j*32 + (((ns*2 + (g >> 2)) ^ (q << 1)) << 2) + (g & 3)];
                    if (r == 0) b0 = fau(to_tf32(v)); else b1 = fau(to_tf32(v));
                }
                mma_tf32(oc[ns], pa, b0, b1);
            }
        }
        __syncthreads();
    }

    #pragma unroll
    for (int ofs = 1; ofs <= 2; ofs <<= 1) {
        lsum0 += __shfl_xor_sync(0xffffffffu, lsum0, ofs);
        lsum1 += __shfl_xor_sync(0xffffffffu, lsum1, ofs);
    }
    float inv0 = 1.0f / lsum0;
    float inv1 = 1.0f / lsum1;

    int r0 = i0 + w*16 + g;
    size_t base0 = (size_t)(b_*NSEQ + r0    )*128 + h*16;
    size_t base1 = (size_t)(b_*NSEQ + r0 + 8)*128 + h*16;
    #pragma unroll
    for (int ns = 0; ns < 4; ++ns) {
        float ax = oc[ns][0]*inv0, ay = oc[ns][1]*inv0;
        float bx = oc[ns][2]*inv1, by = oc[ns][3]*inv1;
        uint32_t ph0, pl0, ph1, pl1;
        PACK2(ph0, ay, ax);
        PACK2(pl0, ay - bfhi(ph0), ax - bflo(ph0));
        PACK2(ph1, by, bx);
        PACK2(pl1, by - bfhi(ph1), bx - bflo(ph1));
        int colp = ns*4 + q;
        g_oh[base0 + colp] = ph0;  g_ol[base0 + colp] = pl0;
        g_oh[base1 + colp] = ph1;  g_ol[base1 + colp] = pl1;
    }
}

// ---------------- launch ----------------------------------------------------
extern "C" void kernel_launch(void* const* d_in, const int* in_sizes, int n_in,
                              void* d_out, int out_size)
{
    const float* x        = (const float*)d_in[0];
    const float* rel_bias = (const float*)d_in[1];
    const float* ln_scale = (const float*)d_in[2];
    const float* w_qkv    = (const float*)d_in[3];
    const float* w_out    = (const float*)d_in[4];
    const float* b_out    = (const float*)d_in[5];
    float*       out      = (float*)d_out;

    ln_kernel<<<ROWS, 128>>>(x, ln_scale);

    {   // pack weights to bf16x2 h/l
        uint32_t *w1h, *w1l, *w2h, *w2l;
        cudaGetSymbolAddress((void**)&w1h, g_w1h);
        cudaGetSymbolAddress((void**)&w1l, g_w1l);
        cudaGetSymbolAddress((void**)&w2h, g_w2h);
        cudaGetSymbolAddress((void**)&w2l, g_w2l);
        int tot1 = (DIM/2)*(3*INNER);     // 196608
        int tot2 = (INNER/2)*DIM;         // 65536
        pack_w_kernel<<<(tot1+255)/256, 256>>>(w_qkv, w1h, w1l, 3*INNER, tot1);
        pack_w_kernel<<<(tot2+255)/256, 256>>>(w_out, w2h, w2l, DIM, tot2);
    }

    dim3 g1(3*INNER/64, ROWS/128);    // (12, 32)
    gemm_qkv_tc<<<g1, 256>>>();

    static int att_attr_set = 0;
    if (!att_attr_set) {
        cudaFuncSetAttribute(attn_mma_kernel,
                             cudaFuncAttributeMaxDynamicSharedMemorySize,
                             ATT_SMEM_BYTES);
        att_attr_set = 1;
    }
    dim3 g2(NSEQ/128, BATCH*HEADS);   // (16, 16)
    attn_mma_kernel<<<g2, 256, ATT_SMEM_BYTES>>>(rel_bias);

    dim3 g3(DIM/64, ROWS/128);        // (8, 32)
    gemm_out_tc<<<g3, 256>>>(b_out, out);
}

// round 15
// speedup vs baseline: 2.0440x; 1.0552x over previous
#include <cuda_runtime.h>
#include <math.h>
#include <cstdint>

#define BATCH  2
#define NSEQ   2048
#define DIM    512
#define HEADS  8
#define DHEAD  32
#define INNER  256
#define ROWS   (BATCH*NSEQ)   // 4096

// ---------------- scratch (device globals) ----------------------------------
__device__ uint32_t g_xn_h[ROWS*DIM/2], g_xn_l[ROWS*DIM/2];   // LN out fp16 h/l
__device__ uint32_t g_w1h[(DIM/2)*(3*INNER)];                 // w_qkv fp16
__device__ uint32_t g_oh[ROWS*INNER/2],  g_ol[ROWS*INNER/2];  // attn O fp16 h/l
__device__ uint32_t g_w2h[(INNER/2)*DIM];                     // w_out fp16
__device__ float g_q[BATCH*HEADS*NSEQ*DHEAD];    // pre-scaled by 1/sqrt(32)
__device__ float g_k[BATCH*HEADS*NSEQ*DHEAD];
__device__ float g_v[BATCH*HEADS*NSEQ*DHEAD];

__device__ __forceinline__ float to_tf32(float x) {
    float r;
    asm("cvt.rna.tf32.f32 %0, %1;" : "=f"(r) : "f"(x));
    return r;
}
__device__ __forceinline__ uint32_t fau(float x) { return __float_as_uint(x); }

__device__ __forceinline__ uint32_t packf16(float hi, float lo) {
    uint32_t r; asm("cvt.rn.f16x2.f32 %0, %1, %2;" : "=r"(r) : "f"(hi), "f"(lo)); return r;
}
__device__ __forceinline__ float f16lo(uint32_t p) {
    float f; asm("{.reg .b16 l,h; mov.b32 {l,h}, %1; cvt.f32.f16 %0, l;}" : "=f"(f) : "r"(p)); return f;
}
__device__ __forceinline__ float f16hi(uint32_t p) {
    float f; asm("{.reg .b16 l,h; mov.b32 {l,h}, %1; cvt.f32.f16 %0, h;}" : "=f"(f) : "r"(p)); return f;
}

__device__ __forceinline__ uint32_t smem_u32(const void* p) {
    uint32_t a;
    asm("{ .reg .u64 t; cvta.to.shared.u64 t, %1; cvt.u32.u64 %0, t; }" : "=r"(a) : "l"(p));
    return a;
}
__device__ __forceinline__ void cp16(uint32_t saddr, const void* g) {
    asm volatile("cp.async.cg.shared.global [%0], [%1], 16;" :: "r"(saddr), "l"(g));
}
#define CP_COMMIT() asm volatile("cp.async.commit_group;" ::: "memory")
#define CP_WAIT(n)  asm volatile("cp.async.wait_group %0;" :: "n"(n) : "memory")

// mma m16n8k8 tf32 (attention, proven)
__device__ __forceinline__ void mma_tf32(float* d, const uint32_t* a,
                                         uint32_t b0, uint32_t b1) {
    asm volatile(
        "mma.sync.aligned.m16n8k8.row.col.f32.tf32.tf32.f32 "
        "{%0,%1,%2,%3}, {%4,%5,%6,%7}, {%8,%9}, {%0,%1,%2,%3};"
        : "+f"(d[0]), "+f"(d[1]), "+f"(d[2]), "+f"(d[3])
        : "r"(a[0]), "r"(a[1]), "r"(a[2]), "r"(a[3]), "r"(b0), "r"(b1));
}
// mma m16n8k16 fp16 (GEMMs)
__device__ __forceinline__ void mma_f16(float* d, const uint32_t* a, const uint32_t* b) {
    asm volatile(
        "mma.sync.aligned.m16n8k16.row.col.f32.f16.f16.f32 "
        "{%0,%1,%2,%3}, {%4,%5,%6,%7}, {%8,%9}, {%0,%1,%2,%3};"
        : "+f"(d[0]), "+f"(d[1]), "+f"(d[2]), "+f"(d[3])
        : "r"(a[0]), "r"(a[1]), "r"(a[2]), "r"(a[3]), "r"(b[0]), "r"(b[1]));
}

// ---------------- 0) weight pack: f32 [K][N] -> fp16x2 [K/2][N] -------------
__global__ __launch_bounds__(256) void pack_w_kernel(const float* __restrict__ w,
                                                     uint32_t* __restrict__ wh,
                                                     int N, int total)
{
    int idx = blockIdx.x*256 + threadIdx.x;
    if (idx >= total) return;
    int kp = idx / N;
    int n  = idx - kp*N;
    float v0 = w[(size_t)(2*kp  )*N + n];
    float v1 = w[(size_t)(2*kp+1)*N + n];
    wh[idx] = packf16(v1, v0);
}

// ---------------- 1) LayerNorm (writes fp16x2 h/l) --------------------------
__global__ __launch_bounds__(128) void ln_kernel(const float* __restrict__ x,
                                                 const float* __restrict__ gamma)
{
    int row = blockIdx.x;
    int t   = threadIdx.x;
    const float* xr = x + (size_t)row*DIM;

    float4 xv = *(const float4*)(xr + t*4);
    float s  = xv.x + xv.y + xv.z + xv.w;
    float ss = xv.x*xv.x + xv.y*xv.y + xv.z*xv.z + xv.w*xv.w;

    #pragma unroll
    for (int ofs = 16; ofs >= 1; ofs >>= 1) {
        s  += __shfl_xor_sync(0xffffffffu, s,  ofs);
        ss += __shfl_xor_sync(0xffffffffu, ss, ofs);
    }
    __shared__ float rs[4], rss[4];
    int lane = t & 31, wid = t >> 5;
    if (lane == 0) { rs[wid] = s; rss[wid] = ss; }
    __syncthreads();
    s  = rs[0]  + rs[1]  + rs[2]  + rs[3];
    ss = rss[0] + rss[1] + rss[2] + rss[3];

    float mu   = s * (1.0f/DIM);
    float var  = ss * (1.0f/DIM) - mu*mu;
    float rstd = rsqrtf(var + 1e-5f);

    float4 g = *(const float4*)(gamma + t*4);
    float4 o;
    o.x = (xv.x - mu) * rstd * g.x;
    o.y = (xv.y - mu) * rstd * g.y;
    o.z = (xv.z - mu) * rstd * g.z;
    o.w = (xv.w - mu) * rstd * g.w;

    uint32_t h0 = packf16(o.y, o.x);
    uint32_t h1 = packf16(o.w, o.z);
    uint32_t l0 = packf16(o.y - f16hi(h0), o.x - f16lo(h0));
    uint32_t l1 = packf16(o.w - f16hi(h1), o.z - f16lo(h1));
    *(uint2*)&g_xn_h[(size_t)row*256 + 2*t] = make_uint2(h0, h1);
    *(uint2*)&g_xn_l[(size_t)row*256 + 2*t] = make_uint2(l0, l1);
}

// ====== fp16 2-term split GEMM core (activation h/l, weight h) ==============
// Block 128x64, BK=32 (16 pairs), 256 thr. Stage (u32): Ah[128][16]@0,
// Al@2048, Bh[16][64]@4096 -> 5120 u32 = 20KB per stage.
template<int KP, int NSTRIDE>
__device__ __forceinline__ void gemm_f16_core(
    const uint32_t* __restrict__ Ah, const uint32_t* __restrict__ Al,
    const uint32_t* __restrict__ Bh,
    uint32_t (*sm)[5120], float c[2][4][4])
{
    const int tid  = threadIdx.x;
    const int lane = tid & 31;
    const int w    = tid >> 5;
    const int wm   = w >> 1, wn = w & 1;
    const int g    = lane >> 2, q = lane & 3;
    const int bm   = blockIdx.y * 128;
    const int bn   = blockIdx.x * 64;
    const int KT   = KP / 16;

    const int arow = tid >> 2, ac4 = tid & 3;
    const int brow = tid >> 4, bc4 = tid & 15;
    const uint32_t aswz = (uint32_t)(ac4 ^ ((arow >> 1) & 3));
    const uint32_t bswz = (uint32_t)(bc4 ^ ((brow & 3) << 1));

    uint32_t sbase[2] = { smem_u32(&sm[0][0]), smem_u32(&sm[1][0]) };

    #define GPREF(SB, T)                                                        \
    do {                                                                        \
        cp16((SB) + (uint32_t)arow*64u + aswz*16u,                              \
             Ah + (size_t)(bm+arow)*KP + (T)*16 + ac4*4);                       \
        cp16((SB) + (uint32_t)(arow+64)*64u + aswz*16u,                         \
             Ah + (size_t)(bm+arow+64)*KP + (T)*16 + ac4*4);                    \
        cp16((SB) + 8192u + (uint32_t)arow*64u + aswz*16u,                      \
             Al + (size_t)(bm+arow)*KP + (T)*16 + ac4*4);                       \
        cp16((SB) + 8192u + (uint32_t)(arow+64)*64u + aswz*16u,                 \
             Al + (size_t)(bm+arow+64)*KP + (T)*16 + ac4*4);                    \
        cp16((SB) + 16384u + (uint32_t)brow*256u + bswz*16u,                    \
             Bh + (size_t)((T)*16+brow)*NSTRIDE + bn + bc4*4);                  \
        CP_COMMIT();                                                            \
    } while (0)

    GPREF(sbase[0], 0);

    for (int t = 0; t < KT; ++t) {
        if (t + 1 < KT) { GPREF(sbase[(t+1) & 1], t+1); CP_WAIT(1); }
        else            { CP_WAIT(0); }
        __syncthreads();

        const uint32_t* sAh = &sm[t & 1][0];
        const uint32_t* sAl = sAh + 2048;
        const uint32_t* sBh = sAh + 4096;

        #pragma unroll
        for (int ks = 0; ks < 2; ++ks) {
            uint32_t ah[2][4], al[2][4];
            #pragma unroll
            for (int i = 0; i < 2; ++i) {
                #pragma unroll
                for (int r = 0; r < 4; ++r) {
                    int row = wm*32 + i*16 + g + 8*(r & 1);
                    int c4  = (ks*2 + (r >> 1)) ^ ((row >> 1) & 3);
                    int idx = row*16 + c4*4 + q;
                    ah[i][r] = sAh[idx];
                    al[i][r] = sAl[idx];
                }
            }
            uint32_t bh[4][2];
            #pragma unroll
            for (int j = 0; j < 4; ++j) {
                #pragma unroll
                for (int r = 0; r < 2; ++r) {
                    int kp = ks*8 + q + 4*r;
                    int n  = wn*32 + j*8 + g;
                    int c4 = (n >> 2) ^ ((kp & 3) << 1);
                    bh[j][r] = sBh[kp*64 + c4*4 + (n & 3)];
                }
            }
            #pragma unroll
            for (int i = 0; i < 2; ++i)
                #pragma unroll
                for (int j = 0; j < 4; ++j) {
                    mma_f16(c[i][j], ah[i], bh[j]);
                    mma_f16(c[i][j], al[i], bh[j]);
                }
        }
        __syncthreads();
    }
    #undef GPREF
}

// ---------------- 2) QKV GEMM (fp16 2-term) ---------------------------------
__global__ __launch_bounds__(256) void gemm_qkv_tc()
{
    __shared__ uint32_t sm[2][5120];
    float c[2][4][4] = {};
    gemm_f16_core<DIM/2, 3*INNER>(g_xn_h, g_xn_l, g_w1h, sm, c);

    int tid  = threadIdx.x;
    int lane = tid & 31;
    int w    = tid >> 5;
    int wm   = w >> 1, wn = w & 1;
    int g    = lane >> 2, q = lane & 3;
    int bm   = blockIdx.y * 128;
    int bn   = blockIdx.x * 64;

    #pragma unroll
    for (int i = 0; i < 2; ++i) {
        int row0 = bm + wm*32 + i*16 + g;
        #pragma unroll
        for (int j = 0; j < 4; ++j) {
            int col  = bn + wn*32 + j*8 + 2*q;
            int part = col >> 8;
            int rest = col & 255;
            int h    = rest >> 5;
            int d    = rest & 31;
            float* dst = (part == 0) ? g_q : (part == 1) ? g_k : g_v;
            float scl  = (part == 0) ? 0.17677669529663687f : 1.0f;
            #pragma unroll
            for (int r = 0; r < 2; ++r) {
                int rm = row0 + r*8;
                int b_ = rm >> 11;
                int n  = rm & 2047;
                float2 o;
                o.x = c[i][j][r*2+0] * scl;
                o.y = c[i][j][r*2+1] * scl;
                *(float2*)(dst + ((size_t)((b_*HEADS + h)*NSEQ + n))*DHEAD + d) = o;
            }
        }
    }
}

// ---------------- 4) Out projection (fp16 2-term) ---------------------------
__global__ __launch_bounds__(256) void gemm_out_tc(const float* __restrict__ bvec,
                                                   float* __restrict__ out)
{
    __shared__ uint32_t sm[2][5120];
    float c[2][4][4] = {};
    gemm_f16_core<INNER/2, DIM>(g_oh, g_ol, g_w2h, sm, c);

    int tid  = threadIdx.x;
    int lane = tid & 31;
    int w    = tid >> 5;
    int wm   = w >> 1, wn = w & 1;
    int g    = lane >> 2, q = lane & 3;
    int bm   = blockIdx.y * 128;
    int bn   = blockIdx.x * 64;

    #pragma unroll
    for (int i = 0; i < 2; ++i) {
        int row0 = bm + wm*32 + i*16 + g;
        #pragma unroll
        for (int j = 0; j < 4; ++j) {
            int col = bn + wn*32 + j*8 + 2*q;
            float2 bb = *(const float2*)(bvec + col);
            #pragma unroll
            for (int r = 0; r < 2; ++r) {
                int rm = row0 + r*8;
                float2 o;
                o.x = c[i][j][r*2+0] + bb.x;
                o.y = c[i][j][r*2+1] + bb.y;
                *(float2*)(out + (size_t)rm*DIM + col) = o;
            }
        }
    }
}

// ---------------- 3) Attention: cp.async pipelined tf32 mma (R10 PROVEN) ----
#define ATT_SMEM_BYTES (24576*4)

__global__ __launch_bounds__(256) void attn_mma_kernel(const float* __restrict__ bias)
{
    extern __shared__ float smem[];

    int tid  = threadIdx.x;
    int w    = tid >> 5;
    int lane = tid & 31;
    int g    = lane >> 2;
    int q    = lane & 3;
    int bh   = blockIdx.y;
    int i0   = blockIdx.x * 128;
    int h    = bh & 7;
    int b_   = bh >> 3;

    const float* qb = g_q + (size_t)bh*NSEQ*DHEAD;
    const float* kb = g_k + (size_t)bh*NSEQ*DHEAD;
    const float* vb = g_v + (size_t)bh*NSEQ*DHEAD;
    const float* bp = bias + (size_t)h*NSEQ*NSEQ + (size_t)i0*NSEQ;

    {
        float* qs = smem + 16384;
        #pragma unroll
        for (int u = 0; u < 4; ++u) {
            int f   = u*256 + tid;
            int row = f >> 3;
            int dg  = (f & 7) * 4;
            float4 qv = *(const float4*)(qb + (size_t)(i0+row)*DHEAD + dg);
            float* s  = &qs[row*33 + dg];
            s[0] = qv.x; s[1] = qv.y; s[2] = qv.z; s[3] = qv.w;
        }
    }
    __syncthreads();

    uint32_t qa[4][4];
    {
        const float* qs = smem + 16384;
        int r0 = w*16 + g;
        #pragma unroll
        for (int ks = 0; ks < 4; ++ks) {
            qa[ks][0] = fau(to_tf32(qs[(r0  )*33 + ks*8 + q    ]));
            qa[ks][1] = fau(to_tf32(qs[(r0+8)*33 + ks*8 + q    ]));
            qa[ks][2] = fau(to_tf32(qs[(r0  )*33 + ks*8 + q + 4]));
            qa[ks][3] = fau(to_tf32(qs[(r0+8)*33 + ks*8 + q + 4]));
        }
    }
    __syncthreads();

    uint32_t s_kv[2] = { smem_u32(smem), smem_u32(smem + 4096) };
    uint32_t s_bi[2] = { smem_u32(smem + 8192), smem_u32(smem + 16384) };

    #define PREFETCH_TILE(stg, JT)                                                 \
    do {                                                                           \
        _Pragma("unroll")                                                          \
        for (int u = 0; u < 2; ++u) {                                              \
            int f   = u*256 + tid;                                                 \
            int row = f >> 3;                                                      \
            int c4  = f & 7;                                                       \
            cp16(s_kv[stg] + (uint32_t)((row*8 + (c4 ^ (row & 7))) << 4),          \
                 kb + (size_t)((JT)+row)*DHEAD + c4*4);                            \
            cp16(s_kv[stg] + 8192u + (uint32_t)((row*8 + (c4 ^ ((row & 3) << 1))) << 4), \
                 vb + (size_t)((JT)+row)*DHEAD + c4*4);                            \
        }                                                                          \
        _Pragma("unroll")                                                          \
        for (int u = 0; u < 8; ++u) {                                              \
            int f   = u*256 + tid;                                                 \
            int row = f >> 4;                                                      \
            int c4  = f & 15;                                                      \
            cp16(s_bi[stg] + (uint32_t)((row*16 + (c4 ^ (row & 15))) << 4),        \
                 bp + (size_t)row*NSEQ + (JT) + c4*4);                             \
        }                                                                          \
        CP_COMMIT();                                                               \
    } while (0)

    PREFETCH_TILE(0, 0);

    float oc[4][4] = {};
    float lsum0 = 0.f, lsum1 = 0.f;
    const int r0l = w*16 + g;

    for (int it = 0; it < 32; ++it) {
        if (it + 1 < 32) {
            PREFETCH_TILE((it+1) & 1, (it+1)*64);
            CP_WAIT(1);
        } else {
            CP_WAIT(0);
        }
        __syncthreads();

        const float* Ks = smem + (it & 1)*4096;
        const float* Vs = Ks + 2048;
        const float* Bs = smem + 8192 + (it & 1)*8192;

        float c[8][4] = {};
        #pragma unroll
        for (int js = 0; js < 8; ++js) {
            #pragma unroll
            for (int ks = 0; ks < 4; ++ks) {
                uint32_t b0, b1;
                #pragma unroll
                for (int r = 0; r < 2; ++r) {
                    float v = Ks[(js*8 + g)*32 + (((ks*2 + r) ^ g) << 2) + q];
                    if (r == 0) b0 = fau(to_tf32(v)); else b1 = fau(to_tf32(v));
                }
                mma_tf32(c[js], qa[ks], b0, b1);
            }
        }

        #pragma unroll
        for (int s = 0; s < 8; ++s) {
            int c4l = s*2 + (q >> 1);
            int e   = 2*(q & 1);
            float2 bv0 = *(const float2*)&Bs[(r0l  )*64 + ((c4l ^ ( r0l      & 15)) << 2) + e];
            float2 bv1 = *(const float2*)&Bs[(r0l+8)*64 + ((c4l ^ ((r0l + 8) & 15)) << 2) + e];
            float p0 = __expf(c[s][0] + bv0.x);
            float p1 = __expf(c[s][1] + bv0.y);
            float p2 = __expf(c[s][2] + bv1.x);
            float p3 = __expf(c[s][3] + bv1.y);
            lsum0 += p0 + p1;
            lsum1 += p2 + p3;
            c[s][0] = to_tf32(p0); c[s][1] = to_tf32(p1);
            c[s][2] = to_tf32(p2); c[s][3] = to_tf32(p3);
        }

        #pragma unroll
        for (int ks = 0; ks < 8; ++ks) {
            int src0 = (lane & ~3) | (q >> 1);
            int src1 = src0 + 2;
            float t0 = __shfl_sync(0xffffffffu, c[ks][0], src0);
            float t1 = __shfl_sync(0xffffffffu, c[ks][1], src0);
            float t2 = __shfl_sync(0xffffffffu, c[ks][2], src0);
            float t3 = __shfl_sync(0xffffffffu, c[ks][3], src0);
            float u0 = __shfl_sync(0xffffffffu, c[ks][0], src1);
            float u1 = __shfl_sync(0xffffffffu, c[ks][1], src1);
            float u2 = __shfl_sync(0xffffffffu, c[ks][2], src1);
            float u3 = __shfl_sync(0xffffffffu, c[ks][3], src1);
            bool odd = (q & 1);
            uint32_t pa[4];
            pa[0] = fau(odd ? t1 : t0);
            pa[1] = fau(odd ? t3 : t2);
            pa[2] = fau(odd ? u1 : u0);
            pa[3] = fau(odd ? u3 : u2);
            #pragma unroll
            for (int ns = 0; ns < 4; ++ns) {
                uint32_t b0, b1;
                #pragma unroll
                for (int r = 0; r < 2; ++r) {
                    int j = ks*8 + q + 4*r;
                    float v = Vs[j*32 + (((ns*2 + (g >> 2)) ^ (q << 1)) << 2) + (g & 3)];
                    if (r == 0) b0 = fau(to_tf32(v)); else b1 = fau(to_tf32(v));
                }
                mma_tf32(oc[ns], pa, b0, b1);
            }
        }
        __syncthreads();
    }

    #pragma unroll
    for (int ofs = 1; ofs <= 2; ofs <<= 1) {
        lsum0 += __shfl_xor_sync(0xffffffffu, lsum0, ofs);
        lsum1 += __shfl_xor_sync(0xffffffffu, lsum1, ofs);
    }
    float inv0 = 1.0f / lsum0;
    float inv1 = 1.0f / lsum1;

    int r0 = i0 + w*16 + g;
    size_t base0 = (size_t)(b_*NSEQ + r0    )*128 + h*16;
    size_t base1 = (size_t)(b_*NSEQ + r0 + 8)*128 + h*16;
    #pragma unroll
    for (int ns = 0; ns < 4; ++ns) {
        float ax = oc[ns][0]*inv0, ay = oc[ns][1]*inv0;
        float bx = oc[ns][2]*inv1, by = oc[ns][3]*inv1;
        uint32_t ph0 = packf16(ay, ax);
        uint32_t pl0 = packf16(ay - f16hi(ph0), ax - f16lo(ph0));
        uint32_t ph1 = packf16(by, bx);
        uint32_t pl1 = packf16(by - f16hi(ph1), bx - f16lo(ph1));
        int colp = ns*4 + q;
        g_oh[base0 + colp] = ph0;  g_ol[base0 + colp] = pl0;
        g_oh[base1 + colp] = ph1;  g_ol[base1 + colp] = pl1;
    }
}

// ---------------- launch ----------------------------------------------------
extern "C" void kernel_launch(void* const* d_in, const int* in_sizes, int n_in,
                              void* d_out, int out_size)
{
    const float* x        = (const float*)d_in[0];
    const float* rel_bias = (const float*)d_in[1];
    const float* ln_scale = (const float*)d_in[2];
    const float* w_qkv    = (const float*)d_in[3];
    const float* w_out    = (const float*)d_in[4];
    const float* b_out    = (const float*)d_in[5];
    float*       out      = (float*)d_out;

    ln_kernel<<<ROWS, 128>>>(x, ln_scale);

    {   // pack weights to fp16
        uint32_t *w1h, *w2h;
        cudaGetSymbolAddress((void**)&w1h, g_w1h);
        cudaGetSymbolAddress((void**)&w2h, g_w2h);
        int tot1 = (DIM/2)*(3*INNER);
        int tot2 = (INNER/2)*DIM;
        pack_w_kernel<<<(tot1+255)/256, 256>>>(w_qkv, w1h, 3*INNER, tot1);
        pack_w_kernel<<<(tot2+255)/256, 256>>>(w_out, w2h, DIM, tot2);
    }

    dim3 g1(3*INNER/64, ROWS/128);    // (12, 32)
    gemm_qkv_tc<<<g1, 256>>>();

    static int att_attr_set = 0;
    if (!att_attr_set) {
        cudaFuncSetAttribute(attn_mma_kernel,
                             cudaFuncAttributeMaxDynamicSharedMemorySize,
                             ATT_SMEM_BYTES);
        att_attr_set = 1;
    }
    dim3 g2(NSEQ/128, BATCH*HEADS);   // (16, 16)
    attn_mma_kernel<<<g2, 256, ATT_SMEM_BYTES>>>(rel_bias);

    dim3 g3(DIM/64, ROWS/128);        // (8, 32)
    gemm_out_tc<<<g3, 256>>>(b_out, out);
}

// round 16
// speedup vs baseline: 2.7921x; 1.3660x over previous
#include <cuda_runtime.h>
#include <math.h>
#include <cstdint>

#define BATCH  2
#define NSEQ   2048
#define DIM    512
#define HEADS  8
#define DHEAD  32
#define INNER  256
#define ROWS   (BATCH*NSEQ)   // 4096

// ---------------- scratch (device globals) ----------------------------------
__device__ uint32_t g_xn_h[ROWS*DIM/2], g_xn_l[ROWS*DIM/2];   // LN out fp16 h/l
__device__ uint32_t g_w1h[(DIM/2)*(3*INNER)];                 // w_qkv fp16
__device__ uint32_t g_oh[ROWS*INNER/2],  g_ol[ROWS*INNER/2];  // attn O fp16 h/l
__device__ uint32_t g_w2h[(INNER/2)*DIM];                     // w_out fp16
__device__ uint32_t g_qp[BATCH*HEADS*NSEQ*16];   // Q fp16x2 pairs along d, pre-scaled
__device__ uint32_t g_kp[BATCH*HEADS*NSEQ*16];   // K fp16x2 pairs along d
__device__ float    g_v [BATCH*HEADS*NSEQ*DHEAD];// V fp32 [bh][n][d]
__device__ uint32_t g_vp[BATCH*HEADS*32*1024];   // V fp16x2 [bh][d][jp] pairs along n

__device__ __forceinline__ uint32_t fau(float x) { return __float_as_uint(x); }

__device__ __forceinline__ uint32_t packf16(float hi, float lo) {
    uint32_t r; asm("cvt.rn.f16x2.f32 %0, %1, %2;" : "=r"(r) : "f"(hi), "f"(lo)); return r;
}
__device__ __forceinline__ float f16lo(uint32_t p) {
    float f; asm("{.reg .b16 l,h; mov.b32 {l,h}, %1; cvt.f32.f16 %0, l;}" : "=f"(f) : "r"(p)); return f;
}
__device__ __forceinline__ float f16hi(uint32_t p) {
    float f; asm("{.reg .b16 l,h; mov.b32 {l,h}, %1; cvt.f32.f16 %0, h;}" : "=f"(f) : "r"(p)); return f;
}

__device__ __forceinline__ uint32_t smem_u32(const void* p) {
    uint32_t a;
    asm("{ .reg .u64 t; cvta.to.shared.u64 t, %1; cvt.u32.u64 %0, t; }" : "=r"(a) : "l"(p));
    return a;
}
__device__ __forceinline__ void cp16(uint32_t saddr, const void* g) {
    asm volatile("cp.async.cg.shared.global [%0], [%1], 16;" :: "r"(saddr), "l"(g));
}
#define CP_COMMIT() asm volatile("cp.async.commit_group;" ::: "memory")
#define CP_WAIT(n)  asm volatile("cp.async.wait_group %0;" :: "n"(n) : "memory")

// mma m16n8k16 fp16 (GEMMs + attention)
__device__ __forceinline__ void mma_f16(float* d, const uint32_t* a, const uint32_t* b) {
    asm volatile(
        "mma.sync.aligned.m16n8k16.row.col.f32.f16.f16.f32 "
        "{%0,%1,%2,%3}, {%4,%5,%6,%7}, {%8,%9}, {%0,%1,%2,%3};"
        : "+f"(d[0]), "+f"(d[1]), "+f"(d[2]), "+f"(d[3])
        : "r"(a[0]), "r"(a[1]), "r"(a[2]), "r"(a[3]), "r"(b[0]), "r"(b[1]));
}

// ---------------- 0) weight pack: f32 [K][N] -> fp16x2 [K/2][N] -------------
__global__ __launch_bounds__(256) void pack_w_kernel(const float* __restrict__ w,
                                                     uint32_t* __restrict__ wh,
                                                     int N, int total)
{
    int idx = blockIdx.x*256 + threadIdx.x;
    if (idx >= total) return;
    int kp = idx / N;
    int n  = idx - kp*N;
    float v0 = w[(size_t)(2*kp  )*N + n];
    float v1 = w[(size_t)(2*kp+1)*N + n];
    wh[idx] = packf16(v1, v0);
}

// ---------------- 0b) V repack: [bh][n][d] f32 -> [bh][d][jp] fp16x2 --------
__global__ __launch_bounds__(256) void vpack_kernel()
{
    __shared__ float vs[128][33];
    int tid = threadIdx.x;
    int bh  = blockIdx.y;
    int n0  = blockIdx.x * 128;

    #pragma unroll
    for (int u = 0; u < 4; ++u) {
        int f   = u*256 + tid;
        int row = f >> 3;
        int dg  = (f & 7) * 4;
        float4 vv = *(const float4*)(g_v + ((size_t)bh*NSEQ + n0 + row)*DHEAD + dg);
        vs[row][dg+0] = vv.x; vs[row][dg+1] = vv.y;
        vs[row][dg+2] = vv.z; vs[row][dg+3] = vv.w;
    }
    __syncthreads();

    int d  = tid >> 3;
    int j8 = (tid & 7) * 8;
    uint32_t* dst = g_vp + ((size_t)bh*32 + d)*1024 + (n0 >> 1) + j8;
    #pragma unroll
    for (int k = 0; k < 8; ++k) {
        int jp = j8 + k;
        dst[k] = packf16(vs[2*jp+1][d], vs[2*jp][d]);
    }
}

// ---------------- 1) LayerNorm (writes fp16x2 h/l) --------------------------
__global__ __launch_bounds__(128) void ln_kernel(const float* __restrict__ x,
                                                 const float* __restrict__ gamma)
{
    int row = blockIdx.x;
    int t   = threadIdx.x;
    const float* xr = x + (size_t)row*DIM;

    float4 xv = *(const float4*)(xr + t*4);
    float s  = xv.x + xv.y + xv.z + xv.w;
    float ss = xv.x*xv.x + xv.y*xv.y + xv.z*xv.z + xv.w*xv.w;

    #pragma unroll
    for (int ofs = 16; ofs >= 1; ofs >>= 1) {
        s  += __shfl_xor_sync(0xffffffffu, s,  ofs);
        ss += __shfl_xor_sync(0xffffffffu, ss, ofs);
    }
    __shared__ float rs[4], rss[4];
    int lane = t & 31, wid = t >> 5;
    if (lane == 0) { rs[wid] = s; rss[wid] = ss; }
    __syncthreads();
    s  = rs[0]  + rs[1]  + rs[2]  + rs[3];
    ss = rss[0] + rss[1] + rss[2] + rss[3];

    float mu   = s * (1.0f/DIM);
    float var  = ss * (1.0f/DIM) - mu*mu;
    float rstd = rsqrtf(var + 1e-5f);

    float4 g = *(const float4*)(gamma + t*4);
    float4 o;
    o.x = (xv.x - mu) * rstd * g.x;
    o.y = (xv.y - mu) * rstd * g.y;
    o.z = (xv.z - mu) * rstd * g.z;
    o.w = (xv.w - mu) * rstd * g.w;

    uint32_t h0 = packf16(o.y, o.x);
    uint32_t h1 = packf16(o.w, o.z);
    uint32_t l0 = packf16(o.y - f16hi(h0), o.x - f16lo(h0));
    uint32_t l1 = packf16(o.w - f16hi(h1), o.z - f16lo(h1));
    *(uint2*)&g_xn_h[(size_t)row*256 + 2*t] = make_uint2(h0, h1);
    *(uint2*)&g_xn_l[(size_t)row*256 + 2*t] = make_uint2(l0, l1);
}

// ====== fp16 2-term split GEMM core (R15 proven) ============================
template<int KP, int NSTRIDE>
__device__ __forceinline__ void gemm_f16_core(
    const uint32_t* __restrict__ Ah, const uint32_t* __restrict__ Al,
    const uint32_t* __restrict__ Bh,
    uint32_t (*sm)[5120], float c[2][4][4])
{
    const int tid  = threadIdx.x;
    const int lane = tid & 31;
    const int w    = tid >> 5;
    const int wm   = w >> 1, wn = w & 1;
    const int g    = lane >> 2, q = lane & 3;
    const int bm   = blockIdx.y * 128;
    const int bn   = blockIdx.x * 64;
    const int KT   = KP / 16;

    const int arow = tid >> 2, ac4 = tid & 3;
    const int brow = tid >> 4, bc4 = tid & 15;
    const uint32_t aswz = (uint32_t)(ac4 ^ ((arow >> 1) & 3));
    const uint32_t bswz = (uint32_t)(bc4 ^ ((brow & 3) << 1));

    uint32_t sbase[2] = { smem_u32(&sm[0][0]), smem_u32(&sm[1][0]) };

    #define GPREF(SB, T)                                                        \
    do {                                                                        \
        cp16((SB) + (uint32_t)arow*64u + aswz*16u,                              \
             Ah + (size_t)(bm+arow)*KP + (T)*16 + ac4*4);                       \
        cp16((SB) + (uint32_t)(arow+64)*64u + aswz*16u,                         \
             Ah + (size_t)(bm+arow+64)*KP + (T)*16 + ac4*4);                    \
        cp16((SB) + 8192u + (uint32_t)arow*64u + aswz*16u,                      \
             Al + (size_t)(bm+arow)*KP + (T)*16 + ac4*4);                       \
        cp16((SB) + 8192u + (uint32_t)(arow+64)*64u + aswz*16u,                 \
             Al + (size_t)(bm+arow+64)*KP + (T)*16 + ac4*4);                    \
        cp16((SB) + 16384u + (uint32_t)brow*256u + bswz*16u,                    \
             Bh + (size_t)((T)*16+brow)*NSTRIDE + bn + bc4*4);                  \
        CP_COMMIT();                                                            \
    } while (0)

    GPREF(sbase[0], 0);

    for (int t = 0; t < KT; ++t) {
        if (t + 1 < KT) { GPREF(sbase[(t+1) & 1], t+1); CP_WAIT(1); }
        else            { CP_WAIT(0); }
        __syncthreads();

        const uint32_t* sAh = &sm[t & 1][0];
        const uint32_t* sAl = sAh + 2048;
        const uint32_t* sBh = sAh + 4096;

        #pragma unroll
        for (int ks = 0; ks < 2; ++ks) {
            uint32_t ah[2][4], al[2][4];
            #pragma unroll
            for (int i = 0; i < 2; ++i) {
                #pragma unroll
                for (int r = 0; r < 4; ++r) {
                    int row = wm*32 + i*16 + g + 8*(r & 1);
                    int c4  = (ks*2 + (r >> 1)) ^ ((row >> 1) & 3);
                    int idx = row*16 + c4*4 + q;
                    ah[i][r] = sAh[idx];
                    al[i][r] = sAl[idx];
                }
            }
            uint32_t bh[4][2];
            #pragma unroll
            for (int j = 0; j < 4; ++j) {
                #pragma unroll
                for (int r = 0; r < 2; ++r) {
                    int kp = ks*8 + q + 4*r;
                    int n  = wn*32 + j*8 + g;
                    int c4 = (n >> 2) ^ ((kp & 3) << 1);
                    bh[j][r] = sBh[kp*64 + c4*4 + (n & 3)];
                }
            }
            #pragma unroll
            for (int i = 0; i < 2; ++i)
                #pragma unroll
                for (int j = 0; j < 4; ++j) {
                    mma_f16(c[i][j], ah[i], bh[j]);
                    mma_f16(c[i][j], al[i], bh[j]);
                }
        }
        __syncthreads();
    }
    #undef GPREF
}

// ---------------- 2) QKV GEMM (fp16 2-term) ---------------------------------
__global__ __launch_bounds__(256) void gemm_qkv_tc()
{
    __shared__ uint32_t sm[2][5120];
    float c[2][4][4] = {};
    gemm_f16_core<DIM/2, 3*INNER>(g_xn_h, g_xn_l, g_w1h, sm, c);

    int tid  = threadIdx.x;
    int lane = tid & 31;
    int w    = tid >> 5;
    int wm   = w >> 1, wn = w & 1;
    int g    = lane >> 2, q = lane & 3;
    int bm   = blockIdx.y * 128;
    int bn   = blockIdx.x * 64;

    #pragma unroll
    for (int i = 0; i < 2; ++i) {
        int row0 = bm + wm*32 + i*16 + g;
        #pragma unroll
        for (int j = 0; j < 4; ++j) {
            int col  = bn + wn*32 + j*8 + 2*q;
            int part = col >> 8;
            int rest = col & 255;
            int h    = rest >> 5;
            int d    = rest & 31;
            #pragma unroll
            for (int r = 0; r < 2; ++r) {
                int rm = row0 + r*8;
                int b_ = rm >> 11;
                int n  = rm & 2047;
                int bh = b_*HEADS + h;
                float v0 = c[i][j][r*2+0];
                float v1 = c[i][j][r*2+1];
                if (part == 0) {
                    const float scl = 0.17677669529663687f;
                    g_qp[((size_t)bh*NSEQ + n)*16 + (d >> 1)] =
                        packf16(v1*scl, v0*scl);
                } else if (part == 1) {
                    g_kp[((size_t)bh*NSEQ + n)*16 + (d >> 1)] = packf16(v1, v0);
                } else {
                    float2 o; o.x = v0; o.y = v1;
                    *(float2*)(g_v + ((size_t)bh*NSEQ + n)*DHEAD + d) = o;
                }
            }
        }
    }
}

// ---------------- 4) Out projection (fp16 2-term) ---------------------------
__global__ __launch_bounds__(256) void gemm_out_tc(const float* __restrict__ bvec,
                                                   float* __restrict__ out)
{
    __shared__ uint32_t sm[2][5120];
    float c[2][4][4] = {};
    gemm_f16_core<INNER/2, DIM>(g_oh, g_ol, g_w2h, sm, c);

    int tid  = threadIdx.x;
    int lane = tid & 31;
    int w    = tid >> 5;
    int wm   = w >> 1, wn = w & 1;
    int g    = lane >> 2, q = lane & 3;
    int bm   = blockIdx.y * 128;
    int bn   = blockIdx.x * 64;

    #pragma unroll
    for (int i = 0; i < 2; ++i) {
        int row0 = bm + wm*32 + i*16 + g;
        #pragma unroll
        for (int j = 0; j < 4; ++j) {
            int col = bn + wn*32 + j*8 + 2*q;
            float2 bb = *(const float2*)(bvec + col);
            #pragma unroll
            for (int r = 0; r < 2; ++r) {
                int rm = row0 + r*8;
                float2 o;
                o.x = c[i][j][r*2+0] + bb.x;
                o.y = c[i][j][r*2+1] + bb.y;
                *(float2*)(out + (size_t)rm*DIM + col) = o;
            }
        }
    }
}

// ---------------- 3) Attention: fp16 k16 mma, cp.async pipelined ------------
// Stage (u32): kp[64 rows][stride 20] @0 (1280), vp[32 rows][stride 36] @1280
// (1152). kv stage = 2432 u32; bias f32 [128][16 f4 swz] @8192/@16384.
#define ATT_SMEM_BYTES (24576*4)

__global__ __launch_bounds__(256) void attn_mma_kernel(const float* __restrict__ bias)
{
    extern __shared__ float smem[];
    uint32_t* smemu = (uint32_t*)smem;

    int tid  = threadIdx.x;
    int w    = tid >> 5;
    int lane = tid & 31;
    int g    = lane >> 2;
    int q    = lane & 3;
    int bh   = blockIdx.y;
    int i0   = blockIdx.x * 128;
    int h    = bh & 7;
    int b_   = bh >> 3;

    const uint32_t* kpg = g_kp + (size_t)bh*NSEQ*16;
    const uint32_t* vpg = g_vp + (size_t)bh*32*1024;
    const float*    bp  = bias + (size_t)h*NSEQ*NSEQ + (size_t)i0*NSEQ;

    // ---- Q a-frags direct from gmem (fp16x2 packed pairs along d) ----
    uint32_t qa[2][4];
    {
        const uint32_t* qpg = g_qp + ((size_t)bh*NSEQ + i0)*16;
        int r0 = w*16 + g;
        #pragma unroll
        for (int ks = 0; ks < 2; ++ks) {
            qa[ks][0] = qpg[(size_t)(r0    )*16 + ks*8 + q    ];
            qa[ks][1] = qpg[(size_t)(r0 + 8)*16 + ks*8 + q    ];
            qa[ks][2] = qpg[(size_t)(r0    )*16 + ks*8 + q + 4];
            qa[ks][3] = qpg[(size_t)(r0 + 8)*16 + ks*8 + q + 4];
        }
    }

    uint32_t sb = smem_u32(smem);

    #define PREFETCH_TILE(stg, JT)                                               \
    do {                                                                         \
        uint32_t kvo = sb + (uint32_t)(stg)*(2432u*4u);                          \
        {   /* K: 64 rows x 16 u32, row stride 20 */                             \
            int r = tid >> 2, seg = tid & 3;                                     \
            cp16(kvo + (uint32_t)(r*20 + seg*4)*4u,                              \
                 kpg + (size_t)((JT) + r)*16 + seg*4);                           \
        }                                                                        \
        {   /* V: 32 rows x 8 u32-of-4, row stride 36 */                         \
            int r = tid >> 3, seg = tid & 7;                                     \
            cp16(kvo + (1280u + (uint32_t)(r*36 + seg*4))*4u,                    \
                 vpg + (size_t)r*1024 + ((JT) >> 1) + seg*4);                    \
        }                                                                        \
        {   /* bias: 128 rows x 16 float4, swz c4^=row&15 */                     \
            uint32_t bo = sb + (8192u + (uint32_t)(stg)*8192u)*4u;               \
            _Pragma("unroll")                                                    \
            for (int u = 0; u < 8; ++u) {                                        \
                int f   = u*256 + tid;                                           \
                int row = f >> 4;                                                \
                int c4  = f & 15;                                                \
                cp16(bo + (uint32_t)((row*16 + (c4 ^ (row & 15))) << 4),         \
                     bp + (size_t)row*NSEQ + (JT) + c4*4);                       \
            }                                                                    \
        }                                                                        \
        CP_COMMIT();                                                             \
    } while (0)

    PREFETCH_TILE(0, 0);

    float oc[4][4] = {};
    float lsum0 = 0.f, lsum1 = 0.f;
    const int r0l = w*16 + g;

    for (int it = 0; it < 32; ++it) {
        if (it + 1 < 32) {
            PREFETCH_TILE((it+1) & 1, (it+1)*64);
            CP_WAIT(1);
        } else {
            CP_WAIT(0);
        }
        __syncthreads();

        const uint32_t* Ks = smemu + (it & 1)*2432;
        const uint32_t* Vs = Ks + 1280;
        const float*    Bs = smem + 8192 + (it & 1)*8192;

        // ---- S = Q K^T : 8 js x 2 k16-chunks ----
        float c[8][4] = {};
        #pragma unroll
        for (int js = 0; js < 8; ++js) {
            int rb = (js*8 + g)*20;
            #pragma unroll
            for (int ks = 0; ks < 2; ++ks) {
                uint32_t bb[2];
                bb[0] = Ks[rb + ks*8 + q    ];
                bb[1] = Ks[rb + ks*8 + q + 4];
                mma_f16(c[js], qa[ks], bb);
            }
        }

        // ---- softmax: bias from smem, exp, row sums ----
        #pragma unroll
        for (int s = 0; s < 8; ++s) {
            int c4l = s*2 + (q >> 1);
            int e   = 2*(q & 1);
            float2 bv0 = *(const float2*)&Bs[(r0l  )*64 + ((c4l ^ ( r0l      & 15)) << 2) + e];
            float2 bv1 = *(const float2*)&Bs[(r0l+8)*64 + ((c4l ^ ((r0l + 8) & 15)) << 2) + e];
            c[s][0] = __expf(c[s][0] + bv0.x);
            c[s][1] = __expf(c[s][1] + bv0.y);
            c[s][2] = __expf(c[s][2] + bv1.x);
            c[s][3] = __expf(c[s][3] + bv1.y);
            lsum0 += c[s][0] + c[s][1];
            lsum1 += c[s][2] + c[s][3];
        }

        // ---- O += P V : c-frags ARE the a-frags (pack only, no shuffles) ----
        #pragma unroll
        for (int m = 0; m < 4; ++m) {
            uint32_t pa[4];
            pa[0] = packf16(c[2*m  ][1], c[2*m  ][0]);
            pa[1] = packf16(c[2*m  ][3], c[2*m  ][2]);
            pa[2] = packf16(c[2*m+1][1], c[2*m+1][0]);
            pa[3] = packf16(c[2*m+1][3], c[2*m+1][2]);
            #pragma unroll
            for (int ns = 0; ns < 4; ++ns) {
                int rb = (ns*8 + g)*36;
                uint32_t bb[2];
                bb[0] = Vs[rb + m*8 + q    ];
                bb[1] = Vs[rb + m*8 + q + 4];
                mma_f16(oc[ns], pa, bb);
            }
        }
        __syncthreads();
    }

    // ---- finalize: reduce l over quad, normalize, store fp16 h/l ----
    #pragma unroll
    for (int ofs = 1; ofs <= 2; ofs <<= 1) {
        lsum0 += __shfl_xor_sync(0xffffffffu, lsum0, ofs);
        lsum1 += __shfl_xor_sync(0xffffffffu, lsum1, ofs);
    }
    float inv0 = 1.0f / lsum0;
    float inv1 = 1.0f / lsum1;

    int r0 = i0 + w*16 + g;
    size_t base0 = (size_t)(b_*NSEQ + r0    )*128 + h*16;
    size_t base1 = (size_t)(b_*NSEQ + r0 + 8)*128 + h*16;
    #pragma unroll
    for (int ns = 0; ns < 4; ++ns) {
        float ax = oc[ns][0]*inv0, ay = oc[ns][1]*inv0;
        float bx = oc[ns][2]*inv1, by = oc[ns][3]*inv1;
        uint32_t ph0 = packf16(ay, ax);
        uint32_t pl0 = packf16(ay - f16hi(ph0), ax - f16lo(ph0));
        uint32_t ph1 = packf16(by, bx);
        uint32_t pl1 = packf16(by - f16hi(ph1), bx - f16lo(ph1));
        int colp = ns*4 + q;
        g_oh[base0 + colp] = ph0;  g_ol[base0 + colp] = pl0;
        g_oh[base1 + colp] = ph1;  g_ol[base1 + colp] = pl1;
    }
}

// ---------------- launch ----------------------------------------------------
extern "C" void kernel_launch(void* const* d_in, const int* in_sizes, int n_in,
                              void* d_out, int out_size)
{
    const float* x        = (const float*)d_in[0];
    const float* rel_bias = (const float*)d_in[1];
    const float* ln_scale = (const float*)d_in[2];
    const float* w_qkv    = (const float*)d_in[3];
    const float* w_out    = (const float*)d_in[4];
    const float* b_out    = (const float*)d_in[5];
    float*       out      = (float*)d_out;

    ln_kernel<<<ROWS, 128>>>(x, ln_scale);

    {   // pack weights to fp16
        uint32_t *w1h, *w2h;
        cudaGetSymbolAddress((void**)&w1h, g_w1h);
        cudaGetSymbolAddress((void**)&w2h, g_w2h);
        int tot1 = (DIM/2)*(3*INNER);
        int tot2 = (INNER/2)*DIM;
        pack_w_kernel<<<(tot1+255)/256, 256>>>(w_qkv, w1h, 3*INNER, tot1);
        pack_w_kernel<<<(tot2+255)/256, 256>>>(w_out, w2h, DIM, tot2);
    }

    dim3 g1(3*INNER/64, ROWS/128);    // (12, 32)
    gemm_qkv_tc<<<g1, 256>>>();

    dim3 gv(NSEQ/128, BATCH*HEADS);   // (16, 16)
    vpack_kernel<<<gv, 256>>>();

    static int att_attr_set = 0;
    if (!att_attr_set) {
        cudaFuncSetAttribute(attn_mma_kernel,
                             cudaFuncAttributeMaxDynamicSharedMemorySize,
                             ATT_SMEM_BYTES);
        att_attr_set = 1;
    }
    dim3 g2(NSEQ/128, BATCH*HEADS);   // (16, 16)
    attn_mma_kernel<<<g2, 256, ATT_SMEM_BYTES>>>(rel_bias);

    dim3 g3(DIM/64, ROWS/128);        // (8, 32)
    gemm_out_tc<<<g3, 256>>>(b_out, out);
}